// round 13
// baseline (speedup 1.0000x reference)
#include <cuda_runtime.h>
#include <cuda_bf16.h>
#include <cuda_fp16.h>
#include <math.h>
#include <stdint.h>

// Problem constants
#define Nn 30000
#define Ee 60000
#define Bb 500
#define Hh 64
#define CWC 1088         // c width: 16 edge slots + bias slot (17*64)

// ---------------- device scratch ----------------
__device__ float g_h0[Nn*Hh];
__device__ float g_h[Nn*Hh];
__device__ __half g_ch[(size_t)Nn*CWC];  // fp16 c
__device__ float g_aggr[Nn*Hh];
__device__ __half g_gh[Nn*4*Hh];         // GRU gemm out [N,256] fp16
__device__ float g_B2L[384*512];         // LSTM combined B (fp32, SIMT path)
__device__ float g_qh[Bb*384];           // [q(128) | rvec(128) | hs(128)]
__device__ float g_cs[Bb*128];
__device__ float g_gts[Bb*512];
__device__ float g_gf[Bb*1024];
__device__ float g_t1[Bb*128];
__device__ int   g_segs[Bb];
__device__ int   g_sege[Bb];

// weight tables, [n][k] layout (K contiguous)
__device__ __half g_BtC[1152*64];                                // c GEMM B: single fp16
__device__ __half g_Bt2_hi[256*128], g_Bt2_lo[256*128];          // GRU B: fp16 hi/lo
__device__ __nv_bfloat16 g_BtP_hi[64*64],  g_BtP_lo[64*64];      // proj B: bf16 hi/lo

__device__ __forceinline__ float sigf(float x) { return 1.f / (1.f + expf(-x)); }

__device__ __forceinline__ uint32_t smem_u32(const void* p) {
    uint32_t a;
    asm("{ .reg .u64 t; cvta.to.shared.u64 t, %1; cvt.u32.u64 %0, t; }" : "=r"(a) : "l"(p));
    return a;
}

__device__ __forceinline__ uint32_t packbf(float a, float b) {
    __nv_bfloat162 t = __floats2bfloat162_rn(a, b);
    return *(uint32_t*)&t;
}

__device__ __forceinline__ void ldsm_x4(uint32_t (&r)[4], uint32_t addr) {
    asm volatile("ldmatrix.sync.aligned.m8n8.x4.shared.b16 {%0,%1,%2,%3}, [%4];"
        : "=r"(r[0]), "=r"(r[1]), "=r"(r[2]), "=r"(r[3]) : "r"(addr));
}

__device__ __forceinline__ void mma16816(float (&d)[4], const uint32_t (&a)[4],
                                         uint32_t b0, uint32_t b1) {
    asm volatile("mma.sync.aligned.m16n8k16.row.col.f32.bf16.bf16.f32 "
        "{%0,%1,%2,%3}, {%4,%5,%6,%7}, {%8,%9}, {%0,%1,%2,%3};"
        : "+f"(d[0]), "+f"(d[1]), "+f"(d[2]), "+f"(d[3])
        : "r"(a[0]), "r"(a[1]), "r"(a[2]), "r"(a[3]), "r"(b0), "r"(b1));
}

__device__ __forceinline__ void mma16816h(float (&d)[4], const uint32_t (&a)[4],
                                          uint32_t b0, uint32_t b1) {
    asm volatile("mma.sync.aligned.m16n8k16.row.col.f32.f16.f16.f32 "
        "{%0,%1,%2,%3}, {%4,%5,%6,%7}, {%8,%9}, {%0,%1,%2,%3};"
        : "+f"(d[0]), "+f"(d[1]), "+f"(d[2]), "+f"(d[3])
        : "r"(a[0]), "r"(a[1]), "r"(a[2]), "r"(a[3]), "r"(b0), "r"(b1));
}

// ================= fp16 single-pass c-GEMM =================
__global__ __launch_bounds__(256) void cgemm_f16(
    const float* __restrict__ A,
    const __half* __restrict__ Bt,
    int M, int tiles_per_cta, const float* __restrict__ bias)
{
    extern __shared__ __half smh[];
    const int P = 72;
    __half* Am = smh;                    // A: [128][72]
    __half* Bs = smh + 128*P;            // B: [64][72]
    __half* Stg = smh + 192*P;           // stage: [128][72]

    const int tid = threadIdx.x, wid = tid >> 5, lane = tid & 31;
    const int row0 = blockIdx.x * 128;
    const int rows = min(128, M - row0);

    if (rows < 128) {
        for (int i = tid; i < 16*P; i += 256)
            *(uint4*)(Am + i*8) = make_uint4(0, 0, 0, 0);
        __syncthreads();
    }

    for (int idx = tid; idx < rows*8; idx += 256) {
        int r = idx >> 3, c8 = idx & 7;
        const float* ap = A + (size_t)(row0 + r)*64 + c8*8;
        float4 v0 = *(const float4*)ap;
        float4 v1 = *(const float4*)(ap + 4);
        __half2 h0 = __floats2half2_rn(v0.x, v0.y);
        __half2 h1 = __floats2half2_rn(v0.z, v0.w);
        __half2 h2 = __floats2half2_rn(v1.x, v1.y);
        __half2 h3 = __floats2half2_rn(v1.z, v1.w);
        uint4 u = make_uint4(*(uint32_t*)&h0, *(uint32_t*)&h1, *(uint32_t*)&h2, *(uint32_t*)&h3);
        *(uint4*)(Am + r*P + c8*8) = u;
    }

    const int wm = wid & 3, wn = wid >> 2;
    uint32_t aaddr[2], baddr[2];
    {
        uint32_t a_sm = smem_u32(Am);
        uint32_t b_sm = smem_u32(Bs);
#pragma unroll
        for (int i = 0; i < 2; i++) {
            int r = wm*32 + i*16 + (lane & 15);
            int c = (lane >> 4) * 8;
            aaddr[i] = a_sm + (uint32_t)(r*P + c) * 2;
        }
#pragma unroll
        for (int p = 0; p < 2; p++) {
            int r = wn*32 + p*16 + (lane & 7) + ((lane >> 4) << 3);
            int c = ((lane >> 3) & 1) * 8;
            baddr[p] = b_sm + (uint32_t)(r*P + c) * 2;
        }
    }

    for (int it = 0; it < tiles_per_cta; it++) {
        const int tile = blockIdx.y * tiles_per_cta + it;
        const int col0 = tile * 64;

        for (int idx = tid; idx < 64*8; idx += 256) {
            int n = idx >> 3, c8 = idx & 7;
            *(uint4*)(Bs + n*P + c8*8) = *(const uint4*)(Bt + (size_t)(col0 + n)*64 + c8*8);
        }
        __syncthreads();

        float acc[2][4][4];
#pragma unroll
        for (int i = 0; i < 2; i++)
#pragma unroll
            for (int j = 0; j < 4; j++)
#pragma unroll
                for (int q = 0; q < 4; q++) acc[i][j][q] = 0.f;

#pragma unroll
        for (int ks = 0; ks < 4; ks++) {
            uint32_t a0[4], a1[4], b0[4], b1[4];
            ldsm_x4(a0, aaddr[0] + ks*32);
            ldsm_x4(a1, aaddr[1] + ks*32);
            ldsm_x4(b0, baddr[0] + ks*32);
            ldsm_x4(b1, baddr[1] + ks*32);
            mma16816h(acc[0][0], a0, b0[0], b0[1]);
            mma16816h(acc[0][1], a0, b0[2], b0[3]);
            mma16816h(acc[0][2], a0, b1[0], b1[1]);
            mma16816h(acc[0][3], a0, b1[2], b1[3]);
            mma16816h(acc[1][0], a1, b0[0], b0[1]);
            mma16816h(acc[1][1], a1, b0[2], b0[3]);
            mma16816h(acc[1][2], a1, b1[0], b1[1]);
            mma16816h(acc[1][3], a1, b1[2], b1[3]);
        }

        if (tile < 17) {
#pragma unroll
            for (int i = 0; i < 2; i++) {
                int rl0 = wm*32 + i*16 + (lane >> 2);
#pragma unroll
                for (int j = 0; j < 4; j++) {
                    int c64 = wn*32 + j*8 + ((lane & 3) << 1);
#pragma unroll
                    for (int h = 0; h < 2; h++) {
                        int rl = rl0 + h*8;
                        __half2 hv = __floats2half2_rn(acc[i][j][h*2], acc[i][j][h*2+1]);
                        *(__half2*)(Stg + rl*P + c64) = hv;
                    }
                }
            }
            __syncthreads();
            for (int idx = tid; idx < 1024; idx += 256) {
                int r = idx >> 3, c8 = idx & 7;
                if (r < rows) {
                    uint4 v = *(const uint4*)(Stg + r*P + c8*8);
                    *(uint4*)(g_ch + (size_t)(row0 + r)*CWC + col0 + c8*8) = v;
                }
            }
        } else {
#pragma unroll
            for (int i = 0; i < 2; i++) {
                int rl0 = wm*32 + i*16 + (lane >> 2);
#pragma unroll
                for (int j = 0; j < 4; j++) {
                    int c64 = wn*32 + j*8 + ((lane & 3) << 1);
#pragma unroll
                    for (int h = 0; h < 2; h++) {
                        int rl = rl0 + h*8;
                        if (rl >= rows) continue;
                        int row = row0 + rl;
                        float2 v = make_float2(acc[i][j][h*2] + bias[c64],
                                               acc[i][j][h*2+1] + bias[c64+1]);
                        *(float2*)(g_aggr + (size_t)row*64 + c64) = v;
                    }
                }
            }
        }
        __syncthreads();
    }
}

// ================= fp16 2-pass GRU GEMM (R10 version) =================
__global__ __launch_bounds__(256) void ggemm_f16(
    const float* __restrict__ Aaggr, const float* __restrict__ Ah,
    const __half* __restrict__ Bhi, const __half* __restrict__ Blo,
    int M, int tiles_per_cta)
{
    extern __shared__ __half smh[];
    const int P = 136;
    __half* Am = smh;                    // [128][136]
    __half* Bs = smh + 128*P;            // hi [64][136], lo [64][136]
    __half* Stg = smh + 256*P;           // stage [128][72]

    const int tid = threadIdx.x, wid = tid >> 5, lane = tid & 31;
    const int row0 = blockIdx.x * 128;
    const int rows = min(128, M - row0);

    if (rows < 128) {
        for (int i = tid; i < 16*P; i += 256)
            *(uint4*)(Am + i*8) = make_uint4(0, 0, 0, 0);
        __syncthreads();
    }

    for (int idx = tid; idx < rows*16; idx += 256) {
        int r = idx >> 4, c8 = idx & 15;
        const float* ap;
        bool dorelu = (c8 < 8);
        if (dorelu) ap = Aaggr + (size_t)(row0 + r)*64 + c8*8;
        else        ap = Ah    + (size_t)(row0 + r)*64 + (c8 - 8)*8;
        float4 v0 = *(const float4*)ap;
        float4 v1 = *(const float4*)(ap + 4);
        float f[8] = {v0.x, v0.y, v0.z, v0.w, v1.x, v1.y, v1.z, v1.w};
        if (dorelu) {
#pragma unroll
            for (int j = 0; j < 8; j++) f[j] = fmaxf(f[j], 0.f);
        }
        __half2 h0 = __floats2half2_rn(f[0], f[1]);
        __half2 h1 = __floats2half2_rn(f[2], f[3]);
        __half2 h2 = __floats2half2_rn(f[4], f[5]);
        __half2 h3 = __floats2half2_rn(f[6], f[7]);
        uint4 u = make_uint4(*(uint32_t*)&h0, *(uint32_t*)&h1, *(uint32_t*)&h2, *(uint32_t*)&h3);
        *(uint4*)(Am + r*P + c8*8) = u;
    }

    const int wm = wid & 3, wn = wid >> 2;
    uint32_t aaddr[2], baddr[2];
    {
        uint32_t a_sm = smem_u32(Am);
        uint32_t b_sm = smem_u32(Bs);
#pragma unroll
        for (int i = 0; i < 2; i++) {
            int r = wm*32 + i*16 + (lane & 15);
            int c = (lane >> 4) * 8;
            aaddr[i] = a_sm + (uint32_t)(r*P + c) * 2;
        }
#pragma unroll
        for (int p = 0; p < 2; p++) {
            int r = wn*32 + p*16 + (lane & 7) + ((lane >> 4) << 3);
            int c = ((lane >> 3) & 1) * 8;
            baddr[p] = b_sm + (uint32_t)(r*P + c) * 2;
        }
    }
    const uint32_t BLO = (uint32_t)(64*P) * 2;

    for (int it = 0; it < tiles_per_cta; it++) {
        const int tile = blockIdx.y * tiles_per_cta + it;
        const int col0 = tile * 64;

        for (int idx = tid; idx < 64*16; idx += 256) {
            int n = idx >> 4, c8 = idx & 15;
            size_t go = (size_t)(col0 + n)*128 + c8*8;
            *(uint4*)(Bs + n*P + c8*8)        = *(const uint4*)(Bhi + go);
            *(uint4*)(Bs + 64*P + n*P + c8*8) = *(const uint4*)(Blo + go);
        }
        __syncthreads();

        float acc[2][4][4];
#pragma unroll
        for (int i = 0; i < 2; i++)
#pragma unroll
            for (int j = 0; j < 4; j++)
#pragma unroll
                for (int q = 0; q < 4; q++) acc[i][j][q] = 0.f;

#pragma unroll
        for (int pass = 0; pass < 2; pass++) {
            uint32_t bo = pass ? BLO : 0u;
#pragma unroll
            for (int ks = 0; ks < 8; ks++) {
                uint32_t a0[4], a1[4], b0[4], b1[4];
                ldsm_x4(a0, aaddr[0] + ks*32);
                ldsm_x4(a1, aaddr[1] + ks*32);
                ldsm_x4(b0, baddr[0] + bo + ks*32);
                ldsm_x4(b1, baddr[1] + bo + ks*32);
                mma16816h(acc[0][0], a0, b0[0], b0[1]);
                mma16816h(acc[0][1], a0, b0[2], b0[3]);
                mma16816h(acc[0][2], a0, b1[0], b1[1]);
                mma16816h(acc[0][3], a0, b1[2], b1[3]);
                mma16816h(acc[1][0], a1, b0[0], b0[1]);
                mma16816h(acc[1][1], a1, b0[2], b0[3]);
                mma16816h(acc[1][2], a1, b1[0], b1[1]);
                mma16816h(acc[1][3], a1, b1[2], b1[3]);
            }
        }

#pragma unroll
        for (int i = 0; i < 2; i++) {
            int rl0 = wm*32 + i*16 + (lane >> 2);
#pragma unroll
            for (int j = 0; j < 4; j++) {
                int c64 = wn*32 + j*8 + ((lane & 3) << 1);
#pragma unroll
                for (int h = 0; h < 2; h++) {
                    int rl = rl0 + h*8;
                    __half2 hv = __floats2half2_rn(acc[i][j][h*2], acc[i][j][h*2+1]);
                    *(__half2*)(Stg + rl*72 + c64) = hv;
                }
            }
        }
        __syncthreads();
        for (int idx = tid; idx < 1024; idx += 256) {
            int r = idx >> 3, c8 = idx & 7;
            if (r < rows) {
                uint4 v = *(const uint4*)(Stg + r*72 + c8*8);
                *(uint4*)(g_gh + (size_t)(row0 + r)*256 + col0 + c8*8) = v;
            }
        }
        __syncthreads();
    }
}

// ================= bf16x3 HMMA GEMM (h0 only) =================
__global__ __launch_bounds__(256) void mma_gemm(
    const float* __restrict__ A, int lda,
    const __nv_bfloat16* __restrict__ Bhi, const __nv_bfloat16* __restrict__ Blo,
    int Ktot, int M, int K, const float* __restrict__ bias)
{
    extern __shared__ __nv_bfloat16 sm[];
    const int P = K + 8;
    __nv_bfloat16* Ah = sm;
    __nv_bfloat16* Al = sm + 128*P;
    __nv_bfloat16* Bh = sm + 256*P;

    const int tid = threadIdx.x, wid = tid >> 5, lane = tid & 31;
    const int row0 = blockIdx.x * 128;
    const int rows = min(128, M - row0);
    const int kc = K >> 3;

    if (rows < 128) {
        for (int i = tid; i < 32*P; i += 256)
            *(uint4*)(Ah + i*8) = make_uint4(0, 0, 0, 0);
        __syncthreads();
    }

    for (int idx = tid; idx < rows*kc; idx += 256) {
        int r = idx / kc, c8 = idx - r*kc;
        const float* ap = A + (size_t)(row0 + r)*lda + c8*8;
        float4 v0 = *(const float4*)ap;
        float4 v1 = *(const float4*)(ap + 4);
        float f[8] = {v0.x, v0.y, v0.z, v0.w, v1.x, v1.y, v1.z, v1.w};
        float hf[8];
#pragma unroll
        for (int j = 0; j < 8; j++) hf[j] = __bfloat162float(__float2bfloat16(f[j]));
        uint4 uh = make_uint4(packbf(f[0], f[1]), packbf(f[2], f[3]),
                              packbf(f[4], f[5]), packbf(f[6], f[7]));
        uint4 ul = make_uint4(packbf(f[0]-hf[0], f[1]-hf[1]), packbf(f[2]-hf[2], f[3]-hf[3]),
                              packbf(f[4]-hf[4], f[5]-hf[5]), packbf(f[6]-hf[6], f[7]-hf[7]));
        *(uint4*)(Ah + r*P + c8*8) = uh;
        *(uint4*)(Al + r*P + c8*8) = ul;
    }

    const int wm = wid & 3, wn = wid >> 2;
    uint32_t aaddr[2], baddr[2];
    {
        uint32_t a_sm = smem_u32(Ah);
        uint32_t b_sm = smem_u32(Bh);
#pragma unroll
        for (int i = 0; i < 2; i++) {
            int r = wm*32 + i*16 + (lane & 15);
            int c = (lane >> 4) * 8;
            aaddr[i] = a_sm + (uint32_t)(r*P + c) * 2;
        }
#pragma unroll
        for (int p = 0; p < 2; p++) {
            int r = wn*32 + p*16 + (lane & 7) + ((lane >> 4) << 3);
            int c = ((lane >> 3) & 1) * 8;
            baddr[p] = b_sm + (uint32_t)(r*P + c) * 2;
        }
    }
    const uint32_t ALO = (uint32_t)(128*P) * 2;
    const uint32_t BLO = (uint32_t)(64*P) * 2;

    for (int idx = tid; idx < 64*kc; idx += 256) {
        int n = idx / kc, c8 = idx - n*kc;
        size_t go = (size_t)n * Ktot + c8*8;
        *(uint4*)(Bh + n*P + c8*8)        = *(const uint4*)(Bhi + go);
        *(uint4*)(Bh + 64*P + n*P + c8*8) = *(const uint4*)(Blo + go);
    }
    __syncthreads();

    float acc[2][4][4];
#pragma unroll
    for (int i = 0; i < 2; i++)
#pragma unroll
        for (int j = 0; j < 4; j++)
#pragma unroll
            for (int q = 0; q < 4; q++) acc[i][j][q] = 0.f;

#pragma unroll
    for (int pass = 0; pass < 3; pass++) {
        uint32_t ao = (pass == 1) ? ALO : 0u;
        uint32_t bo = (pass == 2) ? BLO : 0u;
        for (int ks = 0; ks < K/16; ks++) {
            uint32_t a0[4], a1[4], b0[4], b1[4];
            ldsm_x4(a0, aaddr[0] + ao + ks*32);
            ldsm_x4(a1, aaddr[1] + ao + ks*32);
            ldsm_x4(b0, baddr[0] + bo + ks*32);
            ldsm_x4(b1, baddr[1] + bo + ks*32);
            mma16816(acc[0][0], a0, b0[0], b0[1]);
            mma16816(acc[0][1], a0, b0[2], b0[3]);
            mma16816(acc[0][2], a0, b1[0], b1[1]);
            mma16816(acc[0][3], a0, b1[2], b1[3]);
            mma16816(acc[1][0], a1, b0[0], b0[1]);
            mma16816(acc[1][1], a1, b0[2], b0[3]);
            mma16816(acc[1][2], a1, b1[0], b1[1]);
            mma16816(acc[1][3], a1, b1[2], b1[3]);
        }
    }

#pragma unroll
    for (int i = 0; i < 2; i++) {
        int rl0 = wm*32 + i*16 + (lane >> 2);
#pragma unroll
        for (int j = 0; j < 4; j++) {
            int c64 = wn*32 + j*8 + ((lane & 3) << 1);
#pragma unroll
            for (int h = 0; h < 2; h++) {
                int rl = rl0 + h*8;
                if (rl >= rows) continue;
                int row = row0 + rl;
                float2 v = make_float2(acc[i][j][h*2], acc[i][j][h*2+1]);
                v.x = fmaxf(v.x + bias[c64], 0.f);
                v.y = fmaxf(v.y + bias[c64+1], 0.f);
                *(float2*)(g_h0 + (size_t)row*64 + c64) = v;
                *(float2*)(g_h  + (size_t)row*64 + c64) = v;
            }
        }
    }
}

// ================= SIMT SGEMM =================
// epi: 0 plain | 3 prelu(acc+bias) | 4 relu(acc+bias)
#define TBM 128
#define TBN 64
#define PA 132
#define PB 68
__global__ __launch_bounds__(256) void sgemm(
    const float* __restrict__ A, int lda,
    const float* __restrict__ Bm, int ldb,
    float* __restrict__ C, int ldc,
    int M, int kt_count, int epi,
    const float* __restrict__ bias,
    const float* __restrict__ prelu_a)
{
    __shared__ float As[64*PA];
    __shared__ float Bs[64*PB];
    int row0 = blockIdx.x * TBM;
    int col0 = blockIdx.y * TBN;
    int tid = threadIdx.x;
    int tr = tid >> 4;
    int tc = tid & 15;

    float acc[8][4];
#pragma unroll
    for (int i = 0; i < 8; i++)
#pragma unroll
        for (int j = 0; j < 4; j++) acc[i][j] = 0.f;

    for (int kt = 0; kt < kt_count; kt++) {
#pragma unroll 8
        for (int i = 0; i < (TBM*64)/256; i++) {
            int idx = tid + i * 256;
            int r = idx >> 6, k = idx & 63;
            int row = row0 + r;
            As[k*PA + r] = (row < M) ? A[(size_t)row*lda + kt*64 + k] : 0.f;
        }
#pragma unroll 4
        for (int i = 0; i < (64*TBN)/(256*4); i++) {
            int idx = tid + i * 256;
            int k = idx >> 4, n4 = idx & 15;
            float4 v = *(const float4*)(Bm + (size_t)(kt*64 + k)*ldb + col0 + n4*4);
            *(float4*)(Bs + k*PB + n4*4) = v;
        }
        __syncthreads();
#pragma unroll 8
        for (int k = 0; k < 64; k++) {
            float4 a0 = *(const float4*)(As + k*PA + tr*8);
            float4 a1 = *(const float4*)(As + k*PA + tr*8 + 4);
            float4 b0 = *(const float4*)(Bs + k*PB + tc*4);
            float a[8] = {a0.x,a0.y,a0.z,a0.w,a1.x,a1.y,a1.z,a1.w};
            float b[4] = {b0.x,b0.y,b0.z,b0.w};
#pragma unroll
            for (int i = 0; i < 8; i++)
#pragma unroll
                for (int j = 0; j < 4; j++) acc[i][j] += a[i] * b[j];
        }
        __syncthreads();
    }

#pragma unroll
    for (int i = 0; i < 8; i++) {
        int row = row0 + tr*8 + i;
        if (row >= M) continue;
#pragma unroll
        for (int j = 0; j < 4; j++) {
            int col = col0 + tc*4 + j;
            float v = acc[i][j];
            if (epi == 3) {
                v += bias[col];
                float a0 = *prelu_a;
                v = (v >= 0.f) ? v : a0 * v;
            } else if (epi == 4) {
                v = fmaxf(v + bias[col], 0.f);
            }
            C[(size_t)row*ldc + col] = v;
        }
    }
}

// ---------------- prep (single fused kernel) ----------------
__device__ __forceinline__ void split_store_bf(__nv_bfloat16* hi, __nv_bfloat16* lo, size_t i, float v) {
    __nv_bfloat16 h = __float2bfloat16(v);
    hi[i] = h;
    lo[i] = __float2bfloat16(v - __bfloat162float(h));
}
__device__ __forceinline__ void split_store_h(__half* hi, __half* lo, size_t i, float v) {
    __half h = __float2half_rn(v);
    hi[i] = h;
    lo[i] = __float2half_rn(v - __half2float(h));
}

__global__ void prep_all(const float* __restrict__ W_edge, const float* __restrict__ b_edge,
                         const float* __restrict__ root,
                         const float* __restrict__ gWih, const float* __restrict__ gWhh,
                         const float* __restrict__ W_proj,
                         const float* __restrict__ lWih, const float* __restrict__ lWhh) {
    int idx = blockIdx.x * blockDim.x + threadIdx.x;
    if (idx < 73728) {                       // BtC [1152][64] single fp16
        int j = idx / 64, k = idx % 64;
        float v;
        if (j < 1088) {
            int ke = j >> 6, o = j & 63;
            v = (ke < 16) ? W_edge[ke*4096 + k*64 + o] : b_edge[k*64 + o];
        } else {
            v = root[k*64 + (j - 1088)];
        }
        g_BtC[(size_t)j*64 + k] = __float2half_rn(v);
    } else if (idx < 73728 + 32768) {        // Bt2 [256][128] fp16 hi/lo
        int i2 = idx - 73728;
        int j = i2 / 128, k = i2 % 128;
        float v;
        if (j < 192) {
            v = (k < 64) ? gWih[j*64 + k] : gWhh[j*64 + (k - 64)];
        } else {
            v = (k < 64) ? 0.f : gWhh[(128 + (j - 192))*64 + (k - 64)];
        }
        split_store_h(g_Bt2_hi, g_Bt2_lo, (size_t)j*128 + k, v);
    } else if (idx < 73728 + 32768 + 4096) { // BtP [64][64] bf16 hi/lo
        int i2 = idx - 73728 - 32768;
        int j = i2 / 64, k = i2 % 64;
        split_store_bf(g_BtP_hi, g_BtP_lo, (size_t)j*64 + k, W_proj[k*64 + j]);
    } else if (idx < 73728 + 32768 + 4096 + 196608) { // B2L [384][512]
        int i2 = idx - 73728 - 32768 - 4096;
        int k = i2 / 512, j = i2 % 512;
        g_B2L[i2] = (k < 256) ? lWih[j*256 + k] : lWhh[j*128 + (k - 256)];
    }
}

// segment bounds from sorted batch (arrays pre-zeroed)
__global__ void seg_mark(const int* __restrict__ batch, int N) {
    int n = blockIdx.x * blockDim.x + threadIdx.x;
    if (n >= N) return;
    int b = batch[n];
    if (n == 0 || batch[n-1] != b) g_segs[b] = n;
    if (n == N-1 || batch[n+1] != b) g_sege[b] = n + 1;
}

// ---------------- message passing ----------------
__global__ void edge_msg(const int* __restrict__ src, const int* __restrict__ dst,
                         const float* __restrict__ ea, int E) {
    int t = blockIdx.x * blockDim.x + threadIdx.x;
    int e = t >> 5, o2 = t & 31;
    if (e >= E) return;
    int s = src[e], d = dst[e];
    const __half2* crow = (const __half2*)(g_ch + (size_t)s * CWC) + o2;
    const float4* ea4 = (const float4*)(ea + (size_t)e * 16);
    float4 e0 = ea4[0], e1 = ea4[1], e2 = ea4[2], e3 = ea4[3];
    float2 acc = __half22float2(crow[16*32]);   // bias slot
#define ACCUM(w, slot) { float2 cc = __half22float2(crow[(slot)*32]); acc.x += (w)*cc.x; acc.y += (w)*cc.y; }
    ACCUM(e0.x, 0)  ACCUM(e0.y, 1)  ACCUM(e0.z, 2)  ACCUM(e0.w, 3)
    ACCUM(e1.x, 4)  ACCUM(e1.y, 5)  ACCUM(e1.z, 6)  ACCUM(e1.w, 7)
    ACCUM(e2.x, 8)  ACCUM(e2.y, 9)  ACCUM(e2.z, 10) ACCUM(e2.w, 11)
    ACCUM(e3.x, 12) ACCUM(e3.y, 13) ACCUM(e3.z, 14) ACCUM(e3.w, 15)
#undef ACCUM
    float* ap = g_aggr + (size_t)d*64 + o2*2;
    atomicAdd(ap, acc.x);
    atomicAdd(ap + 1, acc.y);
}

__global__ void gru_gate(const float* __restrict__ bih, const float* __restrict__ bhh, int N) {
    int t = blockIdx.x * blockDim.x + threadIdx.x;
    int n = t >> 6, o = t & 63;
    if (n >= N) return;
    const __half* gr = g_gh + (size_t)n * 256;
    float r = sigf(__half2float(gr[o]) + bih[o] + bhh[o]);
    float z = sigf(__half2float(gr[64 + o]) + bih[64 + o] + bhh[64 + o]);
    float ghn = __half2float(gr[192 + o]) + bhh[128 + o];
    float gin = __half2float(gr[128 + o]) - __half2float(gr[192 + o]) + bih[128 + o];
    float nn = tanhf(gin + r * ghn);
    float ho = g_h[(size_t)n*64 + o];
    g_h[(size_t)n*64 + o] = (1.f - z) * nn + z * ho;
}

// ---------------- node classifier ----------------
__global__ void p_kernel(const float* __restrict__ Wc, const float* __restrict__ bc,
                         float* __restrict__ out, int N) {
    int warp = (blockIdx.x * blockDim.x + threadIdx.x) >> 5;
    int lane = threadIdx.x & 31;
    if (warp >= N) return;
    const float* hr = g_h + (size_t)warp * 64;
    float s = hr[lane] * Wc[lane] + hr[32 + lane] * Wc[32 + lane];
#pragma unroll
    for (int o = 16; o; o >>= 1) s += __shfl_xor_sync(0xffffffffu, s, o);
    if (lane == 0) out[warp] = s + bc[0];
}

// ---------------- fused Set2Set step ----------------
__global__ __launch_bounds__(128) void s2s_step(
    const float* __restrict__ bih, const float* __restrict__ bhh)
{
    int b = blockIdx.x;
    int t = threadIdx.x, wid = t >> 5, lane = t & 31;
    __shared__ float q[128];
    __shared__ float redm[4], redd[4];
    __shared__ float rvs[4][128];

    const float* g = g_gts + (size_t)b * 512;
    float ig = sigf(g[t]       + bih[t]       + bhh[t]);
    float fg = sigf(g[128 + t] + bih[128 + t] + bhh[128 + t]);
    float gg = tanhf(g[256 + t] + bih[256 + t] + bhh[256 + t]);
    float og = sigf(g[384 + t] + bih[384 + t] + bhh[384 + t]);
    float c = fg * g_cs[b*128 + t] + ig * gg;
    g_cs[b*128 + t] = c;
    float h = og * tanhf(c);
    q[t] = h;
    float* qh = g_qh + (size_t)b * 384;
    qh[t] = h;
    qh[256 + t] = h;
    __syncthreads();

    int s0 = g_segs[b], s1 = g_sege[b];

    float mx = -INFINITY;
    for (int n = s0 + wid; n < s1; n += 4) {
        const float* h0r = g_h0 + (size_t)n * 64;
        const float* hr  = g_h  + (size_t)n * 64;
        float s = h0r[lane]*q[lane] + h0r[32+lane]*q[32+lane]
                + hr[lane]*q[64+lane] + hr[32+lane]*q[96+lane];
#pragma unroll
        for (int o = 16; o; o >>= 1) s += __shfl_xor_sync(0xffffffffu, s, o);
        mx = fmaxf(mx, s);
    }
    if (lane == 0) redm[wid] = mx;
    __syncthreads();
    mx = fmaxf(fmaxf(redm[0], redm[1]), fmaxf(redm[2], redm[3]));

    float den = 0.f, rv0 = 0.f, rv1 = 0.f, rv2 = 0.f, rv3 = 0.f;
    for (int n = s0 + wid; n < s1; n += 4) {
        const float* h0r = g_h0 + (size_t)n * 64;
        const float* hr  = g_h  + (size_t)n * 64;
        float x0 = h0r[lane], x1 = h0r[32+lane], x2 = hr[lane], x3 = hr[32+lane];
        float s = x0*q[lane] + x1*q[32+lane] + x2*q[64+lane] + x3*q[96+lane];
#pragma unroll
        for (int o = 16; o; o >>= 1) s += __shfl_xor_sync(0xffffffffu, s, o);
        float a = expf(s - mx);
        den += a;
        rv0 += a*x0; rv1 += a*x1; rv2 += a*x2; rv3 += a*x3;
    }
    rvs[wid][lane] = rv0; rvs[wid][32+lane] = rv1;
    rvs[wid][64+lane] = rv2; rvs[wid][96+lane] = rv3;
    if (lane == 0) redd[wid] = den;
    __syncthreads();
    float dtot = redd[0] + redd[1] + redd[2] + redd[3];
    float r = rvs[0][t] + rvs[1][t] + rvs[2][t] + rvs[3][t];
    qh[128 + t] = (s1 > s0) ? r / dtot : 0.f;
}

// ---------------- final y2 dot (warp per graph) ----------------
__global__ void head2(const float* __restrict__ Wy2, const float* __restrict__ by2,
                      float* __restrict__ out, int base, int B) {
    int warp = (blockIdx.x * blockDim.x + threadIdx.x) >> 5;
    int lane = threadIdx.x & 31;
    if (warp >= B) return;
    const float* tr = g_t1 + (size_t)warp * 128;
    float s = tr[lane]*Wy2[lane] + tr[32+lane]*Wy2[32+lane]
            + tr[64+lane]*Wy2[64+lane] + tr[96+lane]*Wy2[96+lane];
#pragma unroll
    for (int o = 16; o; o >>= 1) s += __shfl_xor_sync(0xffffffffu, s, o);
    if (lane == 0) out[base + warp] = s + by2[0];
}

// ---------------- host ----------------
extern "C" void kernel_launch(void* const* d_in, const int* in_sizes, int n_in,
                              void* d_out, int out_size) {
    const float* x         = (const float*)d_in[0];
    const int*   ei        = (const int*)  d_in[1];
    const float* edge_attr = (const float*)d_in[2];
    const int*   batch     = (const int*)  d_in[3];
    const float* W_proj    = (const float*)d_in[4];
    const float* b_proj    = (const float*)d_in[5];
    const float* W_edge    = (const float*)d_in[6];
    const float* b_edge    = (const float*)d_in[7];
    const float* root      = (const float*)d_in[8];
    const float* conv_bias = (const float*)d_in[9];
    const float* gru_W_ih  = (const float*)d_in[10];
    const float* gru_W_hh  = (const float*)d_in[11];
    const float* gru_b_ih  = (const float*)d_in[12];
    const float* gru_b_hh  = (const float*)d_in[13];
    const float* W_cls     = (const float*)d_in[14];
    const float* b_cls     = (const float*)d_in[15];
    const float* lstm_W_ih = (const float*)d_in[16];
    const float* lstm_W_hh = (const float*)d_in[17];
    const float* lstm_b_ih = (const float*)d_in[18];
    const float* lstm_b_hh = (const float*)d_in[19];
    const float* W_sp      = (const float*)d_in[20];
    const float* b_sp      = (const float*)d_in[21];
    const float* prelu_a   = (const float*)d_in[22];
    const float* W_y1      = (const float*)d_in[23];
    const float* b_y1      = (const float*)d_in[24];
    const float* W_y2      = (const float*)d_in[25];
    const float* b_y2      = (const float*)d_in[26];
    float* out = (float*)d_out;

    const int N = in_sizes[0] / 64;   // 30000
    const int E = in_sizes[2] / 16;   // 60000
    const int B = out_size - N;       // 500

    const int* src = ei;
    const int* dst = ei + E;

    float *p_h, *p_aggr, *p_B2L;
    float *p_qh, *p_cs, *p_gts, *p_gf, *p_t1;
    int *p_segs, *p_sege;
    __half *p_BtC, *p_Bt2_hi, *p_Bt2_lo;
    __nv_bfloat16 *p_BtP_hi, *p_BtP_lo;
    cudaGetSymbolAddress((void**)&p_h, g_h);
    cudaGetSymbolAddress((void**)&p_aggr, g_aggr);
    cudaGetSymbolAddress((void**)&p_B2L, g_B2L);
    cudaGetSymbolAddress((void**)&p_qh, g_qh);
    cudaGetSymbolAddress((void**)&p_cs, g_cs);
    cudaGetSymbolAddress((void**)&p_gts, g_gts);
    cudaGetSymbolAddress((void**)&p_gf, g_gf);
    cudaGetSymbolAddress((void**)&p_t1, g_t1);
    cudaGetSymbolAddress((void**)&p_segs, g_segs);
    cudaGetSymbolAddress((void**)&p_sege, g_sege);
    cudaGetSymbolAddress((void**)&p_BtC, g_BtC);
    cudaGetSymbolAddress((void**)&p_Bt2_hi, g_Bt2_hi);
    cudaGetSymbolAddress((void**)&p_Bt2_lo, g_Bt2_lo);
    cudaGetSymbolAddress((void**)&p_BtP_hi, g_BtP_hi);
    cudaGetSymbolAddress((void**)&p_BtP_lo, g_BtP_lo);

    cudaFuncSetAttribute(mma_gemm, cudaFuncAttributeMaxDynamicSharedMemorySize, 104448);
    cudaFuncSetAttribute(cgemm_f16, cudaFuncAttributeMaxDynamicSharedMemorySize, 46080);
    cudaFuncSetAttribute(ggemm_f16, cudaFuncAttributeMaxDynamicSharedMemorySize, 88064);

    // ---- prep + segment bounds ----
    prep_all<<<1200, 256>>>(W_edge, b_edge, root, gru_W_ih, gru_W_hh,
                            W_proj, lstm_W_ih, lstm_W_hh);
    cudaMemsetAsync(p_segs, 0, Bb*sizeof(int));
    cudaMemsetAsync(p_sege, 0, Bb*sizeof(int));
    seg_mark<<<(N + 255)/256, 256>>>(batch, N);

    const int gx = (N + 127) / 128;  // 235
    const int SM64 = 384 * (64 + 8) * 2;    // 55296

    // ---- h0 = relu(x @ W_proj + b_proj) -> h0, h (bf16x3) ----
    {
        dim3 grid(gx, 1);
        mma_gemm<<<grid, 256, SM64>>>(x, 64, p_BtP_hi, p_BtP_lo, 64, N, 64, b_proj);
    }

    // ---- message passing steps ----
    for (int step = 0; step < 3; step++) {
        {
            dim3 grid(gx, 6);
            cgemm_f16<<<grid, 256, 46080>>>(p_h, p_BtC, N, 3, conv_bias);
        }
        edge_msg<<<(E*32 + 255)/256, 256>>>(src, dst, edge_attr, E);
        {
            dim3 grid(gx, 2);
            ggemm_f16<<<grid, 256, 88064>>>(p_aggr, p_h, p_Bt2_hi, p_Bt2_lo, N, 2);
        }
        gru_gate<<<(N*64 + 255)/256, 256>>>(gru_b_ih, gru_b_hh, N);
    }

    // ---- node classifier ----
    p_kernel<<<(N*32 + 255)/256, 256>>>(W_cls, b_cls, out, N);

    // ---- Set2Set (fused) ----
    cudaMemsetAsync(p_qh, 0, (size_t)B*384*sizeof(float));
    cudaMemsetAsync(p_cs, 0, (size_t)B*128*sizeof(float));

    const int gxb = (B + TBM - 1) / TBM;  // 4
    for (int step = 0; step < 3; step++) {
        {
            dim3 grid(gxb, 8);
            sgemm<<<grid, 256>>>(p_qh, 384, p_B2L, 512, p_gts, 512, B, 6, 0, nullptr, nullptr);
        }
        s2s_step<<<B, 128>>>(lstm_b_ih, lstm_b_hh);
    }

    // ---- final head: gf = prelu(q_star @ W_sp + b_sp); t1 = relu(gf @ W_y1 + b_y1); y = t1 @ W_y2 + b_y2 ----
    {
        dim3 grid(gxb, 16);
        sgemm<<<grid, 256>>>(p_qh, 384, W_sp, 1024, p_gf, 1024, B, 4, 3, b_sp, prelu_a);
    }
    {
        dim3 grid(gxb, 2);
        sgemm<<<grid, 256>>>(p_gf, 1024, W_y1, 128, p_t1, 128, B, 16, 4, b_y1, nullptr);
    }
    head2<<<(B*32 + 255)/256, 256>>>(W_y2, b_y2, out, N, B);
}

// round 14
// speedup vs baseline: 1.0874x; 1.0874x over previous
#include <cuda_runtime.h>
#include <cuda_bf16.h>
#include <cuda_fp16.h>
#include <math.h>
#include <stdint.h>

// Problem constants
#define Nn 30000
#define Ee 60000
#define Bb 500
#define Hh 64
#define CWC 1088         // c width: 16 edge slots + bias slot (17*64)

// ---------------- device scratch ----------------
__device__ float g_h0[Nn*Hh];
__device__ float g_h[Nn*Hh];
__device__ __half g_ch[(size_t)Nn*CWC];  // fp16 c
__device__ float g_aggr[Nn*Hh];
__device__ __half g_gh[Nn*4*Hh];         // GRU gemm out [N,256] fp16
__device__ float g_B2L[384*512];         // LSTM combined B (fp32, SIMT path)
__device__ float g_qh[Bb*384];           // [q(128) | rvec(128) | hs(128)]
__device__ float g_cs[Bb*128];
__device__ float g_gts[Bb*512];
__device__ float g_gf[Bb*1024];
__device__ int   g_segs[Bb];
__device__ int   g_sege[Bb];

// weight tables, [n][k] layout (K contiguous)
__device__ __half g_BtC[1152*64];                                // c GEMM B: single fp16
__device__ __half g_Bt2_hi[256*128], g_Bt2_lo[256*128];          // GRU B: fp16 hi/lo
__device__ __nv_bfloat16 g_BtP_hi[64*64],  g_BtP_lo[64*64];      // proj B: bf16 hi/lo

__device__ __forceinline__ float sigf(float x) { return 1.f / (1.f + expf(-x)); }

__device__ __forceinline__ uint32_t smem_u32(const void* p) {
    uint32_t a;
    asm("{ .reg .u64 t; cvta.to.shared.u64 t, %1; cvt.u32.u64 %0, t; }" : "=r"(a) : "l"(p));
    return a;
}

__device__ __forceinline__ uint32_t packbf(float a, float b) {
    __nv_bfloat162 t = __floats2bfloat162_rn(a, b);
    return *(uint32_t*)&t;
}

__device__ __forceinline__ void ldsm_x4(uint32_t (&r)[4], uint32_t addr) {
    asm volatile("ldmatrix.sync.aligned.m8n8.x4.shared.b16 {%0,%1,%2,%3}, [%4];"
        : "=r"(r[0]), "=r"(r[1]), "=r"(r[2]), "=r"(r[3]) : "r"(addr));
}

__device__ __forceinline__ void mma16816(float (&d)[4], const uint32_t (&a)[4],
                                         uint32_t b0, uint32_t b1) {
    asm volatile("mma.sync.aligned.m16n8k16.row.col.f32.bf16.bf16.f32 "
        "{%0,%1,%2,%3}, {%4,%5,%6,%7}, {%8,%9}, {%0,%1,%2,%3};"
        : "+f"(d[0]), "+f"(d[1]), "+f"(d[2]), "+f"(d[3])
        : "r"(a[0]), "r"(a[1]), "r"(a[2]), "r"(a[3]), "r"(b0), "r"(b1));
}

__device__ __forceinline__ void mma16816h(float (&d)[4], const uint32_t (&a)[4],
                                          uint32_t b0, uint32_t b1) {
    asm volatile("mma.sync.aligned.m16n8k16.row.col.f32.f16.f16.f32 "
        "{%0,%1,%2,%3}, {%4,%5,%6,%7}, {%8,%9}, {%0,%1,%2,%3};"
        : "+f"(d[0]), "+f"(d[1]), "+f"(d[2]), "+f"(d[3])
        : "r"(a[0]), "r"(a[1]), "r"(a[2]), "r"(a[3]), "r"(b0), "r"(b1));
}

// ================= fp16 single-pass c-GEMM =================
// A = h (fp32 -> fp16); B single fp16. K=64.
// tiles<17 -> g_ch (fp16, staged coalesced); tile 17 -> g_aggr (+conv_bias)
__global__ __launch_bounds__(256) void cgemm_f16(
    const float* __restrict__ A,
    const __half* __restrict__ Bt,
    int M, int tiles_per_cta, const float* __restrict__ bias)
{
    extern __shared__ __half smh[];
    const int P = 72;
    __half* Am = smh;                    // A: [128][72]
    __half* Bs = smh + 128*P;            // B: [64][72]
    __half* Stg = smh + 192*P;           // stage: [128][72]

    const int tid = threadIdx.x, wid = tid >> 5, lane = tid & 31;
    const int row0 = blockIdx.x * 128;
    const int rows = min(128, M - row0);

    if (rows < 128) {
        for (int i = tid; i < 16*P; i += 256)
            *(uint4*)(Am + i*8) = make_uint4(0, 0, 0, 0);
        __syncthreads();
    }

    // A convert fp32 -> fp16
    for (int idx = tid; idx < rows*8; idx += 256) {
        int r = idx >> 3, c8 = idx & 7;
        const float* ap = A + (size_t)(row0 + r)*64 + c8*8;
        float4 v0 = *(const float4*)ap;
        float4 v1 = *(const float4*)(ap + 4);
        __half2 h0 = __floats2half2_rn(v0.x, v0.y);
        __half2 h1 = __floats2half2_rn(v0.z, v0.w);
        __half2 h2 = __floats2half2_rn(v1.x, v1.y);
        __half2 h3 = __floats2half2_rn(v1.z, v1.w);
        uint4 u = make_uint4(*(uint32_t*)&h0, *(uint32_t*)&h1, *(uint32_t*)&h2, *(uint32_t*)&h3);
        *(uint4*)(Am + r*P + c8*8) = u;
    }

    const int wm = wid & 3, wn = wid >> 2;
    uint32_t aaddr[2], baddr[2];
    {
        uint32_t a_sm = smem_u32(Am);
        uint32_t b_sm = smem_u32(Bs);
#pragma unroll
        for (int i = 0; i < 2; i++) {
            int r = wm*32 + i*16 + (lane & 15);
            int c = (lane >> 4) * 8;
            aaddr[i] = a_sm + (uint32_t)(r*P + c) * 2;
        }
#pragma unroll
        for (int p = 0; p < 2; p++) {
            int r = wn*32 + p*16 + (lane & 7) + ((lane >> 4) << 3);
            int c = ((lane >> 3) & 1) * 8;
            baddr[p] = b_sm + (uint32_t)(r*P + c) * 2;
        }
    }

    for (int it = 0; it < tiles_per_cta; it++) {
        const int tile = blockIdx.y * tiles_per_cta + it;
        const int col0 = tile * 64;

        for (int idx = tid; idx < 64*8; idx += 256) {
            int n = idx >> 3, c8 = idx & 7;
            *(uint4*)(Bs + n*P + c8*8) = *(const uint4*)(Bt + (size_t)(col0 + n)*64 + c8*8);
        }
        __syncthreads();

        float acc[2][4][4];
#pragma unroll
        for (int i = 0; i < 2; i++)
#pragma unroll
            for (int j = 0; j < 4; j++)
#pragma unroll
                for (int q = 0; q < 4; q++) acc[i][j][q] = 0.f;

#pragma unroll
        for (int ks = 0; ks < 4; ks++) {
            uint32_t a0[4], a1[4], b0[4], b1[4];
            ldsm_x4(a0, aaddr[0] + ks*32);
            ldsm_x4(a1, aaddr[1] + ks*32);
            ldsm_x4(b0, baddr[0] + ks*32);
            ldsm_x4(b1, baddr[1] + ks*32);
            mma16816h(acc[0][0], a0, b0[0], b0[1]);
            mma16816h(acc[0][1], a0, b0[2], b0[3]);
            mma16816h(acc[0][2], a0, b1[0], b1[1]);
            mma16816h(acc[0][3], a0, b1[2], b1[3]);
            mma16816h(acc[1][0], a1, b0[0], b0[1]);
            mma16816h(acc[1][1], a1, b0[2], b0[3]);
            mma16816h(acc[1][2], a1, b1[0], b1[1]);
            mma16816h(acc[1][3], a1, b1[2], b1[3]);
        }

        if (tile < 17) {
#pragma unroll
            for (int i = 0; i < 2; i++) {
                int rl0 = wm*32 + i*16 + (lane >> 2);
#pragma unroll
                for (int j = 0; j < 4; j++) {
                    int c64 = wn*32 + j*8 + ((lane & 3) << 1);
#pragma unroll
                    for (int h = 0; h < 2; h++) {
                        int rl = rl0 + h*8;
                        __half2 hv = __floats2half2_rn(acc[i][j][h*2], acc[i][j][h*2+1]);
                        *(__half2*)(Stg + rl*P + c64) = hv;
                    }
                }
            }
            __syncthreads();
            for (int idx = tid; idx < 1024; idx += 256) {
                int r = idx >> 3, c8 = idx & 7;
                if (r < rows) {
                    uint4 v = *(const uint4*)(Stg + r*P + c8*8);
                    *(uint4*)(g_ch + (size_t)(row0 + r)*CWC + col0 + c8*8) = v;
                }
            }
        } else {
#pragma unroll
            for (int i = 0; i < 2; i++) {
                int rl0 = wm*32 + i*16 + (lane >> 2);
#pragma unroll
                for (int j = 0; j < 4; j++) {
                    int c64 = wn*32 + j*8 + ((lane & 3) << 1);
#pragma unroll
                    for (int h = 0; h < 2; h++) {
                        int rl = rl0 + h*8;
                        if (rl >= rows) continue;
                        int row = row0 + rl;
                        float2 v = make_float2(acc[i][j][h*2] + bias[c64],
                                               acc[i][j][h*2+1] + bias[c64+1]);
                        *(float2*)(g_aggr + (size_t)row*64 + c64) = v;
                    }
                }
            }
        }
        __syncthreads();
    }
}

// ================= fp16 2-pass GRU GEMM =================
__global__ __launch_bounds__(256) void ggemm_f16(
    const float* __restrict__ Aaggr, const float* __restrict__ Ah,
    const __half* __restrict__ Bhi, const __half* __restrict__ Blo,
    int M, int tiles_per_cta)
{
    extern __shared__ __half smh[];
    const int P = 136;
    __half* Am = smh;                    // [128][136]
    __half* Bs = smh + 128*P;            // hi [64][136], lo [64][136]
    __half* Stg = smh + 256*P;           // stage [128][72]

    const int tid = threadIdx.x, wid = tid >> 5, lane = tid & 31;
    const int row0 = blockIdx.x * 128;
    const int rows = min(128, M - row0);

    if (rows < 128) {
        for (int i = tid; i < 16*P; i += 256)
            *(uint4*)(Am + i*8) = make_uint4(0, 0, 0, 0);
        __syncthreads();
    }

    for (int idx = tid; idx < rows*16; idx += 256) {
        int r = idx >> 4, c8 = idx & 15;
        const float* ap;
        bool dorelu = (c8 < 8);
        if (dorelu) ap = Aaggr + (size_t)(row0 + r)*64 + c8*8;
        else        ap = Ah    + (size_t)(row0 + r)*64 + (c8 - 8)*8;
        float4 v0 = *(const float4*)ap;
        float4 v1 = *(const float4*)(ap + 4);
        float f[8] = {v0.x, v0.y, v0.z, v0.w, v1.x, v1.y, v1.z, v1.w};
        if (dorelu) {
#pragma unroll
            for (int j = 0; j < 8; j++) f[j] = fmaxf(f[j], 0.f);
        }
        __half2 h0 = __floats2half2_rn(f[0], f[1]);
        __half2 h1 = __floats2half2_rn(f[2], f[3]);
        __half2 h2 = __floats2half2_rn(f[4], f[5]);
        __half2 h3 = __floats2half2_rn(f[6], f[7]);
        uint4 u = make_uint4(*(uint32_t*)&h0, *(uint32_t*)&h1, *(uint32_t*)&h2, *(uint32_t*)&h3);
        *(uint4*)(Am + r*P + c8*8) = u;
    }

    const int wm = wid & 3, wn = wid >> 2;
    uint32_t aaddr[2], baddr[2];
    {
        uint32_t a_sm = smem_u32(Am);
        uint32_t b_sm = smem_u32(Bs);
#pragma unroll
        for (int i = 0; i < 2; i++) {
            int r = wm*32 + i*16 + (lane & 15);
            int c = (lane >> 4) * 8;
            aaddr[i] = a_sm + (uint32_t)(r*P + c) * 2;
        }
#pragma unroll
        for (int p = 0; p < 2; p++) {
            int r = wn*32 + p*16 + (lane & 7) + ((lane >> 4) << 3);
            int c = ((lane >> 3) & 1) * 8;
            baddr[p] = b_sm + (uint32_t)(r*P + c) * 2;
        }
    }
    const uint32_t BLO = (uint32_t)(64*P) * 2;

    for (int it = 0; it < tiles_per_cta; it++) {
        const int tile = blockIdx.y * tiles_per_cta + it;
        const int col0 = tile * 64;

        for (int idx = tid; idx < 64*16; idx += 256) {
            int n = idx >> 4, c8 = idx & 15;
            size_t go = (size_t)(col0 + n)*128 + c8*8;
            *(uint4*)(Bs + n*P + c8*8)        = *(const uint4*)(Bhi + go);
            *(uint4*)(Bs + 64*P + n*P + c8*8) = *(const uint4*)(Blo + go);
        }
        __syncthreads();

        float acc[2][4][4];
#pragma unroll
        for (int i = 0; i < 2; i++)
#pragma unroll
            for (int j = 0; j < 4; j++)
#pragma unroll
                for (int q = 0; q < 4; q++) acc[i][j][q] = 0.f;

#pragma unroll
        for (int pass = 0; pass < 2; pass++) {
            uint32_t bo = pass ? BLO : 0u;
#pragma unroll
            for (int ks = 0; ks < 8; ks++) {
                uint32_t a0[4], a1[4], b0[4], b1[4];
                ldsm_x4(a0, aaddr[0] + ks*32);
                ldsm_x4(a1, aaddr[1] + ks*32);
                ldsm_x4(b0, baddr[0] + bo + ks*32);
                ldsm_x4(b1, baddr[1] + bo + ks*32);
                mma16816h(acc[0][0], a0, b0[0], b0[1]);
                mma16816h(acc[0][1], a0, b0[2], b0[3]);
                mma16816h(acc[0][2], a0, b1[0], b1[1]);
                mma16816h(acc[0][3], a0, b1[2], b1[3]);
                mma16816h(acc[1][0], a1, b0[0], b0[1]);
                mma16816h(acc[1][1], a1, b0[2], b0[3]);
                mma16816h(acc[1][2], a1, b1[0], b1[1]);
                mma16816h(acc[1][3], a1, b1[2], b1[3]);
            }
        }

#pragma unroll
        for (int i = 0; i < 2; i++) {
            int rl0 = wm*32 + i*16 + (lane >> 2);
#pragma unroll
            for (int j = 0; j < 4; j++) {
                int c64 = wn*32 + j*8 + ((lane & 3) << 1);
#pragma unroll
                for (int h = 0; h < 2; h++) {
                    int rl = rl0 + h*8;
                    __half2 hv = __floats2half2_rn(acc[i][j][h*2], acc[i][j][h*2+1]);
                    *(__half2*)(Stg + rl*72 + c64) = hv;
                }
            }
        }
        __syncthreads();
        for (int idx = tid; idx < 1024; idx += 256) {
            int r = idx >> 3, c8 = idx & 7;
            if (r < rows) {
                uint4 v = *(const uint4*)(Stg + r*72 + c8*8);
                *(uint4*)(g_gh + (size_t)(row0 + r)*256 + col0 + c8*8) = v;
            }
        }
        __syncthreads();
    }
}

// ================= bf16x3 HMMA GEMM (h0 only) =================
__global__ __launch_bounds__(256) void mma_gemm(
    const float* __restrict__ A, int lda,
    const __nv_bfloat16* __restrict__ Bhi, const __nv_bfloat16* __restrict__ Blo,
    int Ktot, int M, int K, const float* __restrict__ bias)
{
    extern __shared__ __nv_bfloat16 sm[];
    const int P = K + 8;
    __nv_bfloat16* Ah = sm;
    __nv_bfloat16* Al = sm + 128*P;
    __nv_bfloat16* Bh = sm + 256*P;

    const int tid = threadIdx.x, wid = tid >> 5, lane = tid & 31;
    const int row0 = blockIdx.x * 128;
    const int rows = min(128, M - row0);
    const int kc = K >> 3;

    if (rows < 128) {
        for (int i = tid; i < 32*P; i += 256)
            *(uint4*)(Ah + i*8) = make_uint4(0, 0, 0, 0);
        __syncthreads();
    }

    for (int idx = tid; idx < rows*kc; idx += 256) {
        int r = idx / kc, c8 = idx - r*kc;
        const float* ap = A + (size_t)(row0 + r)*lda + c8*8;
        float4 v0 = *(const float4*)ap;
        float4 v1 = *(const float4*)(ap + 4);
        float f[8] = {v0.x, v0.y, v0.z, v0.w, v1.x, v1.y, v1.z, v1.w};
        float hf[8];
#pragma unroll
        for (int j = 0; j < 8; j++) hf[j] = __bfloat162float(__float2bfloat16(f[j]));
        uint4 uh = make_uint4(packbf(f[0], f[1]), packbf(f[2], f[3]),
                              packbf(f[4], f[5]), packbf(f[6], f[7]));
        uint4 ul = make_uint4(packbf(f[0]-hf[0], f[1]-hf[1]), packbf(f[2]-hf[2], f[3]-hf[3]),
                              packbf(f[4]-hf[4], f[5]-hf[5]), packbf(f[6]-hf[6], f[7]-hf[7]));
        *(uint4*)(Ah + r*P + c8*8) = uh;
        *(uint4*)(Al + r*P + c8*8) = ul;
    }

    const int wm = wid & 3, wn = wid >> 2;
    uint32_t aaddr[2], baddr[2];
    {
        uint32_t a_sm = smem_u32(Ah);
        uint32_t b_sm = smem_u32(Bh);
#pragma unroll
        for (int i = 0; i < 2; i++) {
            int r = wm*32 + i*16 + (lane & 15);
            int c = (lane >> 4) * 8;
            aaddr[i] = a_sm + (uint32_t)(r*P + c) * 2;
        }
#pragma unroll
        for (int p = 0; p < 2; p++) {
            int r = wn*32 + p*16 + (lane & 7) + ((lane >> 4) << 3);
            int c = ((lane >> 3) & 1) * 8;
            baddr[p] = b_sm + (uint32_t)(r*P + c) * 2;
        }
    }
    const uint32_t ALO = (uint32_t)(128*P) * 2;
    const uint32_t BLO = (uint32_t)(64*P) * 2;

    for (int idx = tid; idx < 64*kc; idx += 256) {
        int n = idx / kc, c8 = idx - n*kc;
        size_t go = (size_t)n * Ktot + c8*8;
        *(uint4*)(Bh + n*P + c8*8)        = *(const uint4*)(Bhi + go);
        *(uint4*)(Bh + 64*P + n*P + c8*8) = *(const uint4*)(Blo + go);
    }
    __syncthreads();

    float acc[2][4][4];
#pragma unroll
    for (int i = 0; i < 2; i++)
#pragma unroll
        for (int j = 0; j < 4; j++)
#pragma unroll
            for (int q = 0; q < 4; q++) acc[i][j][q] = 0.f;

#pragma unroll
    for (int pass = 0; pass < 3; pass++) {
        uint32_t ao = (pass == 1) ? ALO : 0u;
        uint32_t bo = (pass == 2) ? BLO : 0u;
        for (int ks = 0; ks < K/16; ks++) {
            uint32_t a0[4], a1[4], b0[4], b1[4];
            ldsm_x4(a0, aaddr[0] + ao + ks*32);
            ldsm_x4(a1, aaddr[1] + ao + ks*32);
            ldsm_x4(b0, baddr[0] + bo + ks*32);
            ldsm_x4(b1, baddr[1] + bo + ks*32);
            mma16816(acc[0][0], a0, b0[0], b0[1]);
            mma16816(acc[0][1], a0, b0[2], b0[3]);
            mma16816(acc[0][2], a0, b1[0], b1[1]);
            mma16816(acc[0][3], a0, b1[2], b1[3]);
            mma16816(acc[1][0], a1, b0[0], b0[1]);
            mma16816(acc[1][1], a1, b0[2], b0[3]);
            mma16816(acc[1][2], a1, b1[0], b1[1]);
            mma16816(acc[1][3], a1, b1[2], b1[3]);
        }
    }

#pragma unroll
    for (int i = 0; i < 2; i++) {
        int rl0 = wm*32 + i*16 + (lane >> 2);
#pragma unroll
        for (int j = 0; j < 4; j++) {
            int c64 = wn*32 + j*8 + ((lane & 3) << 1);
#pragma unroll
            for (int h = 0; h < 2; h++) {
                int rl = rl0 + h*8;
                if (rl >= rows) continue;
                int row = row0 + rl;
                float2 v = make_float2(acc[i][j][h*2], acc[i][j][h*2+1]);
                v.x = fmaxf(v.x + bias[c64], 0.f);
                v.y = fmaxf(v.y + bias[c64+1], 0.f);
                *(float2*)(g_h0 + (size_t)row*64 + c64) = v;
                *(float2*)(g_h  + (size_t)row*64 + c64) = v;
            }
        }
    }
}

// ================= SIMT SGEMM (small Set2Set / head GEMMs) =================
#define TBM 128
#define TBN 64
#define PA 132
#define PB 68
__global__ __launch_bounds__(256) void sgemm(
    const float* __restrict__ A, int lda,
    const float* __restrict__ Bm, int ldb,
    float* __restrict__ C, int ldc,
    int M, int kt_count, int epi,
    const float* __restrict__ bias,
    const float* __restrict__ prelu_a)
{
    __shared__ float As[64*PA];
    __shared__ float Bs[64*PB];
    int row0 = blockIdx.x * TBM;
    int col0 = blockIdx.y * TBN;
    int tid = threadIdx.x;
    int tr = tid >> 4;
    int tc = tid & 15;

    float acc[8][4];
#pragma unroll
    for (int i = 0; i < 8; i++)
#pragma unroll
        for (int j = 0; j < 4; j++) acc[i][j] = 0.f;

    for (int kt = 0; kt < kt_count; kt++) {
#pragma unroll 8
        for (int i = 0; i < (TBM*64)/256; i++) {
            int idx = tid + i * 256;
            int r = idx >> 6, k = idx & 63;
            int row = row0 + r;
            As[k*PA + r] = (row < M) ? A[(size_t)row*lda + kt*64 + k] : 0.f;
        }
#pragma unroll 4
        for (int i = 0; i < (64*TBN)/(256*4); i++) {
            int idx = tid + i * 256;
            int k = idx >> 4, n4 = idx & 15;
            float4 v = *(const float4*)(Bm + (size_t)(kt*64 + k)*ldb + col0 + n4*4);
            *(float4*)(Bs + k*PB + n4*4) = v;
        }
        __syncthreads();
#pragma unroll 8
        for (int k = 0; k < 64; k++) {
            float4 a0 = *(const float4*)(As + k*PA + tr*8);
            float4 a1 = *(const float4*)(As + k*PA + tr*8 + 4);
            float4 b0 = *(const float4*)(Bs + k*PB + tc*4);
            float a[8] = {a0.x,a0.y,a0.z,a0.w,a1.x,a1.y,a1.z,a1.w};
            float b[4] = {b0.x,b0.y,b0.z,b0.w};
#pragma unroll
            for (int i = 0; i < 8; i++)
#pragma unroll
                for (int j = 0; j < 4; j++) acc[i][j] += a[i] * b[j];
        }
        __syncthreads();
    }

#pragma unroll
    for (int i = 0; i < 8; i++) {
        int row = row0 + tr*8 + i;
        if (row >= M) continue;
#pragma unroll
        for (int j = 0; j < 4; j++) {
            int col = col0 + tc*4 + j;
            float v = acc[i][j];
            if (epi == 3) {
                v += bias[col];
                float a0 = *prelu_a;
                v = (v >= 0.f) ? v : a0 * v;
            }
            C[(size_t)row*ldc + col] = v;
        }
    }
}

// ---------------- prep (single fused kernel) ----------------
__device__ __forceinline__ void split_store_bf(__nv_bfloat16* hi, __nv_bfloat16* lo, size_t i, float v) {
    __nv_bfloat16 h = __float2bfloat16(v);
    hi[i] = h;
    lo[i] = __float2bfloat16(v - __bfloat162float(h));
}
__device__ __forceinline__ void split_store_h(__half* hi, __half* lo, size_t i, float v) {
    __half h = __float2half_rn(v);
    hi[i] = h;
    lo[i] = __float2half_rn(v - __half2float(h));
}

__global__ void prep_all(const float* __restrict__ W_edge, const float* __restrict__ b_edge,
                         const float* __restrict__ root,
                         const float* __restrict__ gWih, const float* __restrict__ gWhh,
                         const float* __restrict__ W_proj,
                         const float* __restrict__ lWih, const float* __restrict__ lWhh) {
    int idx = blockIdx.x * blockDim.x + threadIdx.x;
    if (idx < 73728) {                       // BtC [1152][64] single fp16
        int j = idx / 64, k = idx % 64;
        float v;
        if (j < 1088) {
            int ke = j >> 6, o = j & 63;
            v = (ke < 16) ? W_edge[ke*4096 + k*64 + o] : b_edge[k*64 + o];
        } else {
            v = root[k*64 + (j - 1088)];
        }
        g_BtC[(size_t)j*64 + k] = __float2half_rn(v);
    } else if (idx < 73728 + 32768) {        // Bt2 [256][128] fp16 hi/lo
        int i2 = idx - 73728;
        int j = i2 / 128, k = i2 % 128;
        float v;
        if (j < 192) {
            v = (k < 64) ? gWih[j*64 + k] : gWhh[j*64 + (k - 64)];
        } else {
            v = (k < 64) ? 0.f : gWhh[(128 + (j - 192))*64 + (k - 64)];
        }
        split_store_h(g_Bt2_hi, g_Bt2_lo, (size_t)j*128 + k, v);
    } else if (idx < 73728 + 32768 + 4096) { // BtP [64][64] bf16 hi/lo
        int i2 = idx - 73728 - 32768;
        int j = i2 / 64, k = i2 % 64;
        split_store_bf(g_BtP_hi, g_BtP_lo, (size_t)j*64 + k, W_proj[k*64 + j]);
    } else if (idx < 73728 + 32768 + 4096 + 196608) { // B2L [384][512]
        int i2 = idx - 73728 - 32768 - 4096;
        int k = i2 / 512, j = i2 % 512;
        g_B2L[i2] = (k < 256) ? lWih[j*256 + k] : lWhh[j*128 + (k - 256)];
    }
}

// segment bounds from sorted batch (arrays pre-zeroed)
__global__ void seg_mark(const int* __restrict__ batch, int N) {
    int n = blockIdx.x * blockDim.x + threadIdx.x;
    if (n >= N) return;
    int b = batch[n];
    if (n == 0 || batch[n-1] != b) g_segs[b] = n;
    if (n == N-1 || batch[n+1] != b) g_sege[b] = n + 1;
}

// ---------------- message passing ----------------
// warp per edge; each lane loads one ea value, broadcast via shuffle
__global__ void edge_msg(const int* __restrict__ src, const int* __restrict__ dst,
                         const float* __restrict__ ea, int E) {
    int t = blockIdx.x * blockDim.x + threadIdx.x;
    int e = t >> 5, lane = t & 31;
    if (e >= E) return;
    int s = src[e], d = dst[e];
    const __half2* crow = (const __half2*)(g_ch + (size_t)s * CWC) + lane;
    float w = ea[(size_t)e * 16 + (lane & 15)];
    float2 acc = __half22float2(crow[16*32]);   // bias slot
#pragma unroll
    for (int k = 0; k < 16; k++) {
        float wk = __shfl_sync(0xffffffffu, w, k);
        float2 cc = __half22float2(crow[k*32]);
        acc.x += wk * cc.x;
        acc.y += wk * cc.y;
    }
    float* ap = g_aggr + (size_t)d*64 + lane*2;
    atomicAdd(ap, acc.x);
    atomicAdd(ap + 1, acc.y);
}

__global__ void gru_gate(const float* __restrict__ bih, const float* __restrict__ bhh, int N) {
    int t = blockIdx.x * blockDim.x + threadIdx.x;
    int n = t >> 6, o = t & 63;
    if (n >= N) return;
    const __half* gr = g_gh + (size_t)n * 256;
    float r = sigf(__half2float(gr[o]) + bih[o] + bhh[o]);
    float z = sigf(__half2float(gr[64 + o]) + bih[64 + o] + bhh[64 + o]);
    float ghn = __half2float(gr[192 + o]) + bhh[128 + o];
    float gin = __half2float(gr[128 + o]) - __half2float(gr[192 + o]) + bih[128 + o];
    float nn = tanhf(gin + r * ghn);
    float ho = g_h[(size_t)n*64 + o];
    g_h[(size_t)n*64 + o] = (1.f - z) * nn + z * ho;
}

// ---------------- node classifier ----------------
__global__ void p_kernel(const float* __restrict__ Wc, const float* __restrict__ bc,
                         float* __restrict__ out, int N) {
    int warp = (blockIdx.x * blockDim.x + threadIdx.x) >> 5;
    int lane = threadIdx.x & 31;
    if (warp >= N) return;
    const float* hr = g_h + (size_t)warp * 64;
    float s = hr[lane] * Wc[lane] + hr[32 + lane] * Wc[32 + lane];
#pragma unroll
    for (int o = 16; o; o >>= 1) s += __shfl_xor_sync(0xffffffffu, s, o);
    if (lane == 0) out[warp] = s + bc[0];
}

// ---------------- fused Set2Set step ----------------
__global__ __launch_bounds__(128) void s2s_step(
    const float* __restrict__ bih, const float* __restrict__ bhh)
{
    int b = blockIdx.x;
    int t = threadIdx.x, wid = t >> 5, lane = t & 31;
    __shared__ float q[128];
    __shared__ float redm[4], redd[4];
    __shared__ float rvs[4][128];

    const float* g = g_gts + (size_t)b * 512;
    float ig = sigf(g[t]       + bih[t]       + bhh[t]);
    float fg = sigf(g[128 + t] + bih[128 + t] + bhh[128 + t]);
    float gg = tanhf(g[256 + t] + bih[256 + t] + bhh[256 + t]);
    float og = sigf(g[384 + t] + bih[384 + t] + bhh[384 + t]);
    float c = fg * g_cs[b*128 + t] + ig * gg;
    g_cs[b*128 + t] = c;
    float h = og * tanhf(c);
    q[t] = h;
    float* qh = g_qh + (size_t)b * 384;
    qh[t] = h;
    qh[256 + t] = h;
    __syncthreads();

    int s0 = g_segs[b], s1 = g_sege[b];

    float mx = -INFINITY;
    for (int n = s0 + wid; n < s1; n += 4) {
        const float* h0r = g_h0 + (size_t)n * 64;
        const float* hr  = g_h  + (size_t)n * 64;
        float s = h0r[lane]*q[lane] + h0r[32+lane]*q[32+lane]
                + hr[lane]*q[64+lane] + hr[32+lane]*q[96+lane];
#pragma unroll
        for (int o = 16; o; o >>= 1) s += __shfl_xor_sync(0xffffffffu, s, o);
        mx = fmaxf(mx, s);
    }
    if (lane == 0) redm[wid] = mx;
    __syncthreads();
    mx = fmaxf(fmaxf(redm[0], redm[1]), fmaxf(redm[2], redm[3]));

    float den = 0.f, rv0 = 0.f, rv1 = 0.f, rv2 = 0.f, rv3 = 0.f;
    for (int n = s0 + wid; n < s1; n += 4) {
        const float* h0r = g_h0 + (size_t)n * 64;
        const float* hr  = g_h  + (size_t)n * 64;
        float x0 = h0r[lane], x1 = h0r[32+lane], x2 = hr[lane], x3 = hr[32+lane];
        float s = x0*q[lane] + x1*q[32+lane] + x2*q[64+lane] + x3*q[96+lane];
#pragma unroll
        for (int o = 16; o; o >>= 1) s += __shfl_xor_sync(0xffffffffu, s, o);
        float a = expf(s - mx);
        den += a;
        rv0 += a*x0; rv1 += a*x1; rv2 += a*x2; rv3 += a*x3;
    }
    rvs[wid][lane] = rv0; rvs[wid][32+lane] = rv1;
    rvs[wid][64+lane] = rv2; rvs[wid][96+lane] = rv3;
    if (lane == 0) redd[wid] = den;
    __syncthreads();
    float dtot = redd[0] + redd[1] + redd[2] + redd[3];
    float r = rvs[0][t] + rvs[1][t] + rvs[2][t] + rvs[3][t];
    qh[128 + t] = (s1 > s0) ? r / dtot : 0.f;
}

// ---------------- final regressor head ----------------
__global__ void head_kernel(const float* __restrict__ Wy1, const float* __restrict__ by1,
                            const float* __restrict__ Wy2, const float* __restrict__ by2,
                            float* __restrict__ out, int base, int B) {
    int b = blockIdx.x;
    int t = threadIdx.x;
    if (b >= B) return;
    __shared__ float sh_gf[1024];
    for (int i = t; i < 1024; i += 128) sh_gf[i] = g_gf[(size_t)b*1024 + i];
    __syncthreads();
    float s = by1[t];
    for (int r = 0; r < 1024; r++) s += sh_gf[r] * Wy1[r*128 + t];
    s = fmaxf(s, 0.f);
    float v = s * Wy2[t];
    __shared__ float red[128];
    red[t] = v;
    __syncthreads();
    for (int o = 64; o; o >>= 1) {
        if (t < o) red[t] += red[t + o];
        __syncthreads();
    }
    if (t == 0) out[base + b] = red[0] + by2[0];
}

// ---------------- host ----------------
extern "C" void kernel_launch(void* const* d_in, const int* in_sizes, int n_in,
                              void* d_out, int out_size) {
    const float* x         = (const float*)d_in[0];
    const int*   ei        = (const int*)  d_in[1];
    const float* edge_attr = (const float*)d_in[2];
    const int*   batch     = (const int*)  d_in[3];
    const float* W_proj    = (const float*)d_in[4];
    const float* b_proj    = (const float*)d_in[5];
    const float* W_edge    = (const float*)d_in[6];
    const float* b_edge    = (const float*)d_in[7];
    const float* root      = (const float*)d_in[8];
    const float* conv_bias = (const float*)d_in[9];
    const float* gru_W_ih  = (const float*)d_in[10];
    const float* gru_W_hh  = (const float*)d_in[11];
    const float* gru_b_ih  = (const float*)d_in[12];
    const float* gru_b_hh  = (const float*)d_in[13];
    const float* W_cls     = (const float*)d_in[14];
    const float* b_cls     = (const float*)d_in[15];
    const float* lstm_W_ih = (const float*)d_in[16];
    const float* lstm_W_hh = (const float*)d_in[17];
    const float* lstm_b_ih = (const float*)d_in[18];
    const float* lstm_b_hh = (const float*)d_in[19];
    const float* W_sp      = (const float*)d_in[20];
    const float* b_sp      = (const float*)d_in[21];
    const float* prelu_a   = (const float*)d_in[22];
    const float* W_y1      = (const float*)d_in[23];
    const float* b_y1      = (const float*)d_in[24];
    const float* W_y2      = (const float*)d_in[25];
    const float* b_y2      = (const float*)d_in[26];
    float* out = (float*)d_out;

    const int N = in_sizes[0] / 64;   // 30000
    const int E = in_sizes[2] / 16;   // 60000
    const int B = out_size - N;       // 500

    const int* src = ei;
    const int* dst = ei + E;

    float *p_h, *p_aggr, *p_B2L;
    float *p_qh, *p_cs, *p_gts, *p_gf;
    int *p_segs, *p_sege;
    __half *p_BtC, *p_Bt2_hi, *p_Bt2_lo;
    __nv_bfloat16 *p_BtP_hi, *p_BtP_lo;
    cudaGetSymbolAddress((void**)&p_h, g_h);
    cudaGetSymbolAddress((void**)&p_aggr, g_aggr);
    cudaGetSymbolAddress((void**)&p_B2L, g_B2L);
    cudaGetSymbolAddress((void**)&p_qh, g_qh);
    cudaGetSymbolAddress((void**)&p_cs, g_cs);
    cudaGetSymbolAddress((void**)&p_gts, g_gts);
    cudaGetSymbolAddress((void**)&p_gf, g_gf);
    cudaGetSymbolAddress((void**)&p_segs, g_segs);
    cudaGetSymbolAddress((void**)&p_sege, g_sege);
    cudaGetSymbolAddress((void**)&p_BtC, g_BtC);
    cudaGetSymbolAddress((void**)&p_Bt2_hi, g_Bt2_hi);
    cudaGetSymbolAddress((void**)&p_Bt2_lo, g_Bt2_lo);
    cudaGetSymbolAddress((void**)&p_BtP_hi, g_BtP_hi);
    cudaGetSymbolAddress((void**)&p_BtP_lo, g_BtP_lo);

    cudaFuncSetAttribute(mma_gemm, cudaFuncAttributeMaxDynamicSharedMemorySize, 104448);
    cudaFuncSetAttribute(cgemm_f16, cudaFuncAttributeMaxDynamicSharedMemorySize, 46080);
    cudaFuncSetAttribute(ggemm_f16, cudaFuncAttributeMaxDynamicSharedMemorySize, 88064);

    // ---- prep + segment bounds ----
    prep_all<<<1200, 256>>>(W_edge, b_edge, root, gru_W_ih, gru_W_hh,
                            W_proj, lstm_W_ih, lstm_W_hh);
    cudaMemsetAsync(p_segs, 0, Bb*sizeof(int));
    cudaMemsetAsync(p_sege, 0, Bb*sizeof(int));
    seg_mark<<<(N + 255)/256, 256>>>(batch, N);

    const int gx = (N + 127) / 128;  // 235
    const int SM64 = 384 * (64 + 8) * 2;    // 55296

    // ---- h0 = relu(x @ W_proj + b_proj) -> h0, h (bf16x3) ----
    {
        dim3 grid(gx, 1);
        mma_gemm<<<grid, 256, SM64>>>(x, 64, p_BtP_hi, p_BtP_lo, 64, N, 64, b_proj);
    }

    // ---- message passing steps ----
    for (int step = 0; step < 3; step++) {
        // c = h @ [Gr | bias | root] (fp16 single): tiles 0..16 -> g_ch, 17 -> g_aggr
        {
            dim3 grid(gx, 6);
            cgemm_f16<<<grid, 256, 46080>>>(p_h, p_BtC, N, 3, conv_bias);
        }
        edge_msg<<<(E*32 + 255)/256, 256>>>(src, dst, edge_attr, E);
        // g = [relu(aggr) | h] @ B2  [N,256] (fp16 2-pass) -> g_gh fp16
        {
            dim3 grid(gx, 2);
            ggemm_f16<<<grid, 256, 88064>>>(p_aggr, p_h, p_Bt2_hi, p_Bt2_lo, N, 2);
        }
        gru_gate<<<(N*64 + 255)/256, 256>>>(gru_b_ih, gru_b_hh, N);
    }

    // ---- node classifier ----
    p_kernel<<<(N*32 + 255)/256, 256>>>(W_cls, b_cls, out, N);

    // ---- Set2Set (fused) ----
    cudaMemsetAsync(p_qh, 0, (size_t)B*384*sizeof(float));
    cudaMemsetAsync(p_cs, 0, (size_t)B*128*sizeof(float));

    const int gxb = (B + TBM - 1) / TBM;  // 4
    for (int step = 0; step < 3; step++) {
        {
            dim3 grid(gxb, 8);
            sgemm<<<grid, 256>>>(p_qh, 384, p_B2L, 512, p_gts, 512, B, 6, 0, nullptr, nullptr);
        }
        s2s_step<<<B, 128>>>(lstm_b_ih, lstm_b_hh);
    }

    // ---- final head ----
    {
        dim3 grid(gxb, 16);
        sgemm<<<grid, 256>>>(p_qh, 384, W_sp, 1024, p_gf, 1024, B, 4, 3, b_sp, prelu_a);
    }
    head_kernel<<<B, 128>>>(W_y1, b_y1, W_y2, b_y2, out, N, B);
}

// round 15
// speedup vs baseline: 1.2156x; 1.1179x over previous
#include <cuda_runtime.h>
#include <cuda_fp16.h>
#include <math.h>
#include <stdint.h>

// Problem constants
#define Nn 30000
#define Ee 60000
#define Bb 500
#define Hh 64
#define CWC 1088         // c width: 16 edge slots + bias slot (17*64)

// ---------------- device scratch ----------------
__device__ float g_h0[Nn*Hh];
__device__ float g_h[Nn*Hh];
__device__ __half g_ch[(size_t)Nn*CWC];  // fp16 c
__device__ float g_aggr[Nn*Hh];
__device__ __half g_gh[Nn*4*Hh];         // GRU gemm out [N,256] fp16
__device__ float g_B2L[256*512];         // LSTM combined B (hs-folded), fp32
__device__ float g_qh[Bb*256];           // [hs(128) | rvec(128)]
__device__ float g_cs[Bb*128];
__device__ float g_gts[Bb*512];
__device__ float g_gf[Bb*1024];
__device__ int   g_segs[Bb];
__device__ int   g_sege[Bb];

// weight tables, [n][k] layout (K contiguous)
__device__ __half g_BtC[1152*64];                                // c GEMM B: single fp16
__device__ __half g_Bt2_hi[256*128], g_Bt2_lo[256*128];          // GRU B: fp16 hi/lo
__device__ __half g_BtP_hi[64*64],  g_BtP_lo[64*64];             // proj B: fp16 hi/lo

__device__ __forceinline__ float sigf(float x) { return 1.f / (1.f + expf(-x)); }

__device__ __forceinline__ uint32_t smem_u32(const void* p) {
    uint32_t a;
    asm("{ .reg .u64 t; cvta.to.shared.u64 t, %1; cvt.u32.u64 %0, t; }" : "=r"(a) : "l"(p));
    return a;
}

__device__ __forceinline__ void ldsm_x4(uint32_t (&r)[4], uint32_t addr) {
    asm volatile("ldmatrix.sync.aligned.m8n8.x4.shared.b16 {%0,%1,%2,%3}, [%4];"
        : "=r"(r[0]), "=r"(r[1]), "=r"(r[2]), "=r"(r[3]) : "r"(addr));
}

__device__ __forceinline__ void mma16816h(float (&d)[4], const uint32_t (&a)[4],
                                          uint32_t b0, uint32_t b1) {
    asm volatile("mma.sync.aligned.m16n8k16.row.col.f32.f16.f16.f32 "
        "{%0,%1,%2,%3}, {%4,%5,%6,%7}, {%8,%9}, {%0,%1,%2,%3};"
        : "+f"(d[0]), "+f"(d[1]), "+f"(d[2]), "+f"(d[3])
        : "r"(a[0]), "r"(a[1]), "r"(a[2]), "r"(a[3]), "r"(b0), "r"(b1));
}

// ================= fp16 single-pass c-GEMM =================
// A = h (fp32 -> fp16); B single fp16. K=64.
// tiles<17 -> g_ch (fp16, staged coalesced); tile 17 -> g_aggr (+conv_bias)
__global__ __launch_bounds__(256) void cgemm_f16(
    const float* __restrict__ A,
    const __half* __restrict__ Bt,
    int M, int tiles_per_cta, const float* __restrict__ bias)
{
    extern __shared__ __half smh[];
    const int P = 72;
    __half* Am = smh;                    // A: [128][72]
    __half* Bs = smh + 128*P;            // B: [64][72]
    __half* Stg = smh + 192*P;           // stage: [128][72]

    const int tid = threadIdx.x, wid = tid >> 5, lane = tid & 31;
    const int row0 = blockIdx.x * 128;
    const int rows = min(128, M - row0);

    if (rows < 128) {
        for (int i = tid; i < 16*P; i += 256)
            *(uint4*)(Am + i*8) = make_uint4(0, 0, 0, 0);
        __syncthreads();
    }

    for (int idx = tid; idx < rows*8; idx += 256) {
        int r = idx >> 3, c8 = idx & 7;
        const float* ap = A + (size_t)(row0 + r)*64 + c8*8;
        float4 v0 = *(const float4*)ap;
        float4 v1 = *(const float4*)(ap + 4);
        __half2 h0 = __floats2half2_rn(v0.x, v0.y);
        __half2 h1 = __floats2half2_rn(v0.z, v0.w);
        __half2 h2 = __floats2half2_rn(v1.x, v1.y);
        __half2 h3 = __floats2half2_rn(v1.z, v1.w);
        uint4 u = make_uint4(*(uint32_t*)&h0, *(uint32_t*)&h1, *(uint32_t*)&h2, *(uint32_t*)&h3);
        *(uint4*)(Am + r*P + c8*8) = u;
    }

    const int wm = wid & 3, wn = wid >> 2;
    uint32_t aaddr[2], baddr[2];
    {
        uint32_t a_sm = smem_u32(Am);
        uint32_t b_sm = smem_u32(Bs);
#pragma unroll
        for (int i = 0; i < 2; i++) {
            int r = wm*32 + i*16 + (lane & 15);
            int c = (lane >> 4) * 8;
            aaddr[i] = a_sm + (uint32_t)(r*P + c) * 2;
        }
#pragma unroll
        for (int p = 0; p < 2; p++) {
            int r = wn*32 + p*16 + (lane & 7) + ((lane >> 4) << 3);
            int c = ((lane >> 3) & 1) * 8;
            baddr[p] = b_sm + (uint32_t)(r*P + c) * 2;
        }
    }

    for (int it = 0; it < tiles_per_cta; it++) {
        const int tile = blockIdx.y * tiles_per_cta + it;
        const int col0 = tile * 64;

        for (int idx = tid; idx < 64*8; idx += 256) {
            int n = idx >> 3, c8 = idx & 7;
            *(uint4*)(Bs + n*P + c8*8) = *(const uint4*)(Bt + (size_t)(col0 + n)*64 + c8*8);
        }
        __syncthreads();

        float acc[2][4][4];
#pragma unroll
        for (int i = 0; i < 2; i++)
#pragma unroll
            for (int j = 0; j < 4; j++)
#pragma unroll
                for (int q = 0; q < 4; q++) acc[i][j][q] = 0.f;

#pragma unroll
        for (int ks = 0; ks < 4; ks++) {
            uint32_t a0[4], a1[4], b0[4], b1[4];
            ldsm_x4(a0, aaddr[0] + ks*32);
            ldsm_x4(a1, aaddr[1] + ks*32);
            ldsm_x4(b0, baddr[0] + ks*32);
            ldsm_x4(b1, baddr[1] + ks*32);
            mma16816h(acc[0][0], a0, b0[0], b0[1]);
            mma16816h(acc[0][1], a0, b0[2], b0[3]);
            mma16816h(acc[0][2], a0, b1[0], b1[1]);
            mma16816h(acc[0][3], a0, b1[2], b1[3]);
            mma16816h(acc[1][0], a1, b0[0], b0[1]);
            mma16816h(acc[1][1], a1, b0[2], b0[3]);
            mma16816h(acc[1][2], a1, b1[0], b1[1]);
            mma16816h(acc[1][3], a1, b1[2], b1[3]);
        }

        if (tile < 17) {
#pragma unroll
            for (int i = 0; i < 2; i++) {
                int rl0 = wm*32 + i*16 + (lane >> 2);
#pragma unroll
                for (int j = 0; j < 4; j++) {
                    int c64 = wn*32 + j*8 + ((lane & 3) << 1);
#pragma unroll
                    for (int h = 0; h < 2; h++) {
                        int rl = rl0 + h*8;
                        __half2 hv = __floats2half2_rn(acc[i][j][h*2], acc[i][j][h*2+1]);
                        *(__half2*)(Stg + rl*P + c64) = hv;
                    }
                }
            }
            __syncthreads();
            for (int idx = tid; idx < 1024; idx += 256) {
                int r = idx >> 3, c8 = idx & 7;
                if (r < rows) {
                    uint4 v = *(const uint4*)(Stg + r*P + c8*8);
                    *(uint4*)(g_ch + (size_t)(row0 + r)*CWC + col0 + c8*8) = v;
                }
            }
        } else {
#pragma unroll
            for (int i = 0; i < 2; i++) {
                int rl0 = wm*32 + i*16 + (lane >> 2);
#pragma unroll
                for (int j = 0; j < 4; j++) {
                    int c64 = wn*32 + j*8 + ((lane & 3) << 1);
#pragma unroll
                    for (int h = 0; h < 2; h++) {
                        int rl = rl0 + h*8;
                        if (rl >= rows) continue;
                        int row = row0 + rl;
                        float2 v = make_float2(acc[i][j][h*2] + bias[c64],
                                               acc[i][j][h*2+1] + bias[c64+1]);
                        *(float2*)(g_aggr + (size_t)row*64 + c64) = v;
                    }
                }
            }
        }
        __syncthreads();
    }
}

// ================= fp16 2-pass proj GEMM (h0) =================
// A = x (fp32 -> fp16), K=64; B fp16 hi/lo [64][64]. relu(+bias) -> g_h0, g_h
__global__ __launch_bounds__(256) void pgemm_f16(
    const float* __restrict__ A,
    const __half* __restrict__ Bhi, const __half* __restrict__ Blo,
    int M, const float* __restrict__ bias)
{
    extern __shared__ __half smh[];
    const int P = 72;
    __half* Am = smh;                    // [128][72]
    __half* Bs = smh + 128*P;            // hi [64][72], lo [64][72]

    const int tid = threadIdx.x, wid = tid >> 5, lane = tid & 31;
    const int row0 = blockIdx.x * 128;
    const int rows = min(128, M - row0);

    if (rows < 128) {
        for (int i = tid; i < 16*P; i += 256)
            *(uint4*)(Am + i*8) = make_uint4(0, 0, 0, 0);
        __syncthreads();
    }

    for (int idx = tid; idx < rows*8; idx += 256) {
        int r = idx >> 3, c8 = idx & 7;
        const float* ap = A + (size_t)(row0 + r)*64 + c8*8;
        float4 v0 = *(const float4*)ap;
        float4 v1 = *(const float4*)(ap + 4);
        __half2 h0 = __floats2half2_rn(v0.x, v0.y);
        __half2 h1 = __floats2half2_rn(v0.z, v0.w);
        __half2 h2 = __floats2half2_rn(v1.x, v1.y);
        __half2 h3 = __floats2half2_rn(v1.z, v1.w);
        uint4 u = make_uint4(*(uint32_t*)&h0, *(uint32_t*)&h1, *(uint32_t*)&h2, *(uint32_t*)&h3);
        *(uint4*)(Am + r*P + c8*8) = u;
    }

    for (int idx = tid; idx < 64*8; idx += 256) {
        int n = idx >> 3, c8 = idx & 7;
        *(uint4*)(Bs + n*P + c8*8)        = *(const uint4*)(Bhi + (size_t)n*64 + c8*8);
        *(uint4*)(Bs + 64*P + n*P + c8*8) = *(const uint4*)(Blo + (size_t)n*64 + c8*8);
    }
    __syncthreads();

    const int wm = wid & 3, wn = wid >> 2;
    uint32_t aaddr[2], baddr[2];
    {
        uint32_t a_sm = smem_u32(Am);
        uint32_t b_sm = smem_u32(Bs);
#pragma unroll
        for (int i = 0; i < 2; i++) {
            int r = wm*32 + i*16 + (lane & 15);
            int c = (lane >> 4) * 8;
            aaddr[i] = a_sm + (uint32_t)(r*P + c) * 2;
        }
#pragma unroll
        for (int p = 0; p < 2; p++) {
            int r = wn*32 + p*16 + (lane & 7) + ((lane >> 4) << 3);
            int c = ((lane >> 3) & 1) * 8;
            baddr[p] = b_sm + (uint32_t)(r*P + c) * 2;
        }
    }
    const uint32_t BLO = (uint32_t)(64*P) * 2;

    float acc[2][4][4];
#pragma unroll
    for (int i = 0; i < 2; i++)
#pragma unroll
        for (int j = 0; j < 4; j++)
#pragma unroll
            for (int q = 0; q < 4; q++) acc[i][j][q] = 0.f;

#pragma unroll
    for (int pass = 0; pass < 2; pass++) {
        uint32_t bo = pass ? BLO : 0u;
#pragma unroll
        for (int ks = 0; ks < 4; ks++) {
            uint32_t a0[4], a1[4], b0[4], b1[4];
            ldsm_x4(a0, aaddr[0] + ks*32);
            ldsm_x4(a1, aaddr[1] + ks*32);
            ldsm_x4(b0, baddr[0] + bo + ks*32);
            ldsm_x4(b1, baddr[1] + bo + ks*32);
            mma16816h(acc[0][0], a0, b0[0], b0[1]);
            mma16816h(acc[0][1], a0, b0[2], b0[3]);
            mma16816h(acc[0][2], a0, b1[0], b1[1]);
            mma16816h(acc[0][3], a0, b1[2], b1[3]);
            mma16816h(acc[1][0], a1, b0[0], b0[1]);
            mma16816h(acc[1][1], a1, b0[2], b0[3]);
            mma16816h(acc[1][2], a1, b1[0], b1[1]);
            mma16816h(acc[1][3], a1, b1[2], b1[3]);
        }
    }

#pragma unroll
    for (int i = 0; i < 2; i++) {
        int rl0 = wm*32 + i*16 + (lane >> 2);
#pragma unroll
        for (int j = 0; j < 4; j++) {
            int c64 = wn*32 + j*8 + ((lane & 3) << 1);
#pragma unroll
            for (int h = 0; h < 2; h++) {
                int rl = rl0 + h*8;
                if (rl >= rows) continue;
                int row = row0 + rl;
                float2 v = make_float2(acc[i][j][h*2], acc[i][j][h*2+1]);
                v.x = fmaxf(v.x + bias[c64], 0.f);
                v.y = fmaxf(v.y + bias[c64+1], 0.f);
                *(float2*)(g_h0 + (size_t)row*64 + c64) = v;
                *(float2*)(g_h  + (size_t)row*64 + c64) = v;
            }
        }
    }
}

// ================= fp16 2-pass GRU GEMM =================
__global__ __launch_bounds__(256) void ggemm_f16(
    const float* __restrict__ Aaggr, const float* __restrict__ Ah,
    const __half* __restrict__ Bhi, const __half* __restrict__ Blo,
    int M, int tiles_per_cta)
{
    extern __shared__ __half smh[];
    const int P = 136;
    __half* Am = smh;                    // [128][136]
    __half* Bs = smh + 128*P;            // hi [64][136], lo [64][136]
    __half* Stg = smh + 256*P;           // stage [128][72]

    const int tid = threadIdx.x, wid = tid >> 5, lane = tid & 31;
    const int row0 = blockIdx.x * 128;
    const int rows = min(128, M - row0);

    if (rows < 128) {
        for (int i = tid; i < 16*P; i += 256)
            *(uint4*)(Am + i*8) = make_uint4(0, 0, 0, 0);
        __syncthreads();
    }

    for (int idx = tid; idx < rows*16; idx += 256) {
        int r = idx >> 4, c8 = idx & 15;
        const float* ap;
        bool dorelu = (c8 < 8);
        if (dorelu) ap = Aaggr + (size_t)(row0 + r)*64 + c8*8;
        else        ap = Ah    + (size_t)(row0 + r)*64 + (c8 - 8)*8;
        float4 v0 = *(const float4*)ap;
        float4 v1 = *(const float4*)(ap + 4);
        float f[8] = {v0.x, v0.y, v0.z, v0.w, v1.x, v1.y, v1.z, v1.w};
        if (dorelu) {
#pragma unroll
            for (int j = 0; j < 8; j++) f[j] = fmaxf(f[j], 0.f);
        }
        __half2 h0 = __floats2half2_rn(f[0], f[1]);
        __half2 h1 = __floats2half2_rn(f[2], f[3]);
        __half2 h2 = __floats2half2_rn(f[4], f[5]);
        __half2 h3 = __floats2half2_rn(f[6], f[7]);
        uint4 u = make_uint4(*(uint32_t*)&h0, *(uint32_t*)&h1, *(uint32_t*)&h2, *(uint32_t*)&h3);
        *(uint4*)(Am + r*P + c8*8) = u;
    }

    const int wm = wid & 3, wn = wid >> 2;
    uint32_t aaddr[2], baddr[2];
    {
        uint32_t a_sm = smem_u32(Am);
        uint32_t b_sm = smem_u32(Bs);
#pragma unroll
        for (int i = 0; i < 2; i++) {
            int r = wm*32 + i*16 + (lane & 15);
            int c = (lane >> 4) * 8;
            aaddr[i] = a_sm + (uint32_t)(r*P + c) * 2;
        }
#pragma unroll
        for (int p = 0; p < 2; p++) {
            int r = wn*32 + p*16 + (lane & 7) + ((lane >> 4) << 3);
            int c = ((lane >> 3) & 1) * 8;
            baddr[p] = b_sm + (uint32_t)(r*P + c) * 2;
        }
    }
    const uint32_t BLO = (uint32_t)(64*P) * 2;

    for (int it = 0; it < tiles_per_cta; it++) {
        const int tile = blockIdx.y * tiles_per_cta + it;
        const int col0 = tile * 64;

        for (int idx = tid; idx < 64*16; idx += 256) {
            int n = idx >> 4, c8 = idx & 15;
            size_t go = (size_t)(col0 + n)*128 + c8*8;
            *(uint4*)(Bs + n*P + c8*8)        = *(const uint4*)(Bhi + go);
            *(uint4*)(Bs + 64*P + n*P + c8*8) = *(const uint4*)(Blo + go);
        }
        __syncthreads();

        float acc[2][4][4];
#pragma unroll
        for (int i = 0; i < 2; i++)
#pragma unroll
            for (int j = 0; j < 4; j++)
#pragma unroll
                for (int q = 0; q < 4; q++) acc[i][j][q] = 0.f;

#pragma unroll
        for (int pass = 0; pass < 2; pass++) {
            uint32_t bo = pass ? BLO : 0u;
#pragma unroll
            for (int ks = 0; ks < 8; ks++) {
                uint32_t a0[4], a1[4], b0[4], b1[4];
                ldsm_x4(a0, aaddr[0] + ks*32);
                ldsm_x4(a1, aaddr[1] + ks*32);
                ldsm_x4(b0, baddr[0] + bo + ks*32);
                ldsm_x4(b1, baddr[1] + bo + ks*32);
                mma16816h(acc[0][0], a0, b0[0], b0[1]);
                mma16816h(acc[0][1], a0, b0[2], b0[3]);
                mma16816h(acc[0][2], a0, b1[0], b1[1]);
                mma16816h(acc[0][3], a0, b1[2], b1[3]);
                mma16816h(acc[1][0], a1, b0[0], b0[1]);
                mma16816h(acc[1][1], a1, b0[2], b0[3]);
                mma16816h(acc[1][2], a1, b1[0], b1[1]);
                mma16816h(acc[1][3], a1, b1[2], b1[3]);
            }
        }

#pragma unroll
        for (int i = 0; i < 2; i++) {
            int rl0 = wm*32 + i*16 + (lane >> 2);
#pragma unroll
            for (int j = 0; j < 4; j++) {
                int c64 = wn*32 + j*8 + ((lane & 3) << 1);
#pragma unroll
                for (int h = 0; h < 2; h++) {
                    int rl = rl0 + h*8;
                    __half2 hv = __floats2half2_rn(acc[i][j][h*2], acc[i][j][h*2+1]);
                    *(__half2*)(Stg + rl*72 + c64) = hv;
                }
            }
        }
        __syncthreads();
        for (int idx = tid; idx < 1024; idx += 256) {
            int r = idx >> 3, c8 = idx & 7;
            if (r < rows) {
                uint4 v = *(const uint4*)(Stg + r*72 + c8*8);
                *(uint4*)(g_gh + (size_t)(row0 + r)*256 + col0 + c8*8) = v;
            }
        }
        __syncthreads();
    }
}

// ================= SIMT SGEMM (small Set2Set / head GEMMs) =================
#define TBM 128
#define TBN 64
#define PA 132
#define PB 68
__global__ __launch_bounds__(256) void sgemm(
    const float* __restrict__ A, int lda,
    const float* __restrict__ Bm, int ldb,
    float* __restrict__ C, int ldc,
    int M, int kt_count, int epi,
    const float* __restrict__ bias,
    const float* __restrict__ prelu_a)
{
    __shared__ float As[64*PA];
    __shared__ float Bs[64*PB];
    int row0 = blockIdx.x * TBM;
    int col0 = blockIdx.y * TBN;
    int tid = threadIdx.x;
    int tr = tid >> 4;
    int tc = tid & 15;

    float acc[8][4];
#pragma unroll
    for (int i = 0; i < 8; i++)
#pragma unroll
        for (int j = 0; j < 4; j++) acc[i][j] = 0.f;

    for (int kt = 0; kt < kt_count; kt++) {
#pragma unroll 8
        for (int i = 0; i < (TBM*64)/256; i++) {
            int idx = tid + i * 256;
            int r = idx >> 6, k = idx & 63;
            int row = row0 + r;
            As[k*PA + r] = (row < M) ? A[(size_t)row*lda + kt*64 + k] : 0.f;
        }
#pragma unroll 4
        for (int i = 0; i < (64*TBN)/(256*4); i++) {
            int idx = tid + i * 256;
            int k = idx >> 4, n4 = idx & 15;
            float4 v = *(const float4*)(Bm + (size_t)(kt*64 + k)*ldb + col0 + n4*4);
            *(float4*)(Bs + k*PB + n4*4) = v;
        }
        __syncthreads();
#pragma unroll 8
        for (int k = 0; k < 64; k++) {
            float4 a0 = *(const float4*)(As + k*PA + tr*8);
            float4 a1 = *(const float4*)(As + k*PA + tr*8 + 4);
            float4 b0 = *(const float4*)(Bs + k*PB + tc*4);
            float a[8] = {a0.x,a0.y,a0.z,a0.w,a1.x,a1.y,a1.z,a1.w};
            float b[4] = {b0.x,b0.y,b0.z,b0.w};
#pragma unroll
            for (int i = 0; i < 8; i++)
#pragma unroll
                for (int j = 0; j < 4; j++) acc[i][j] += a[i] * b[j];
        }
        __syncthreads();
    }

#pragma unroll
    for (int i = 0; i < 8; i++) {
        int row = row0 + tr*8 + i;
        if (row >= M) continue;
#pragma unroll
        for (int j = 0; j < 4; j++) {
            int col = col0 + tc*4 + j;
            float v = acc[i][j];
            if (epi == 3) {
                v += bias[col];
                float a0 = *prelu_a;
                v = (v >= 0.f) ? v : a0 * v;
            }
            C[(size_t)row*ldc + col] = v;
        }
    }
}

// ---------------- prep (single fused kernel) ----------------
__device__ __forceinline__ void split_store_h(__half* hi, __half* lo, size_t i, float v) {
    __half h = __float2half_rn(v);
    hi[i] = h;
    lo[i] = __float2half_rn(v - __half2float(h));
}

__global__ void prep_all(const float* __restrict__ W_edge, const float* __restrict__ b_edge,
                         const float* __restrict__ root,
                         const float* __restrict__ gWih, const float* __restrict__ gWhh,
                         const float* __restrict__ W_proj,
                         const float* __restrict__ lWih, const float* __restrict__ lWhh) {
    int idx = blockIdx.x * blockDim.x + threadIdx.x;
    if (idx < 73728) {                       // BtC [1152][64] single fp16
        int j = idx / 64, k = idx % 64;
        float v;
        if (j < 1088) {
            int ke = j >> 6, o = j & 63;
            v = (ke < 16) ? W_edge[ke*4096 + k*64 + o] : b_edge[k*64 + o];
        } else {
            v = root[k*64 + (j - 1088)];
        }
        g_BtC[(size_t)j*64 + k] = __float2half_rn(v);
    } else if (idx < 73728 + 32768) {        // Bt2 [256][128] fp16 hi/lo
        int i2 = idx - 73728;
        int j = i2 / 128, k = i2 % 128;
        float v;
        if (j < 192) {
            v = (k < 64) ? gWih[j*64 + k] : gWhh[j*64 + (k - 64)];
        } else {
            v = (k < 64) ? 0.f : gWhh[(128 + (j - 192))*64 + (k - 64)];
        }
        split_store_h(g_Bt2_hi, g_Bt2_lo, (size_t)j*128 + k, v);
    } else if (idx < 73728 + 32768 + 4096) { // BtP [64][64] fp16 hi/lo
        int i2 = idx - 73728 - 32768;
        int j = i2 / 64, k = i2 % 64;
        split_store_h(g_BtP_hi, g_BtP_lo, (size_t)j*64 + k, W_proj[k*64 + j]);
    } else if (idx < 73728 + 32768 + 4096 + 131072) { // B2L combined [256][512]
        int i2 = idx - 73728 - 32768 - 4096;
        int k = i2 / 512, j = i2 % 512;
        float v = lWih[j*256 + k];
        if (k < 128) v += lWhh[j*128 + k];   // fold duplicated hs (q == hs)
        g_B2L[i2] = v;
    }
}

// segment bounds from sorted batch (arrays pre-zeroed)
__global__ void seg_mark(const int* __restrict__ batch, int N) {
    int n = blockIdx.x * blockDim.x + threadIdx.x;
    if (n >= N) return;
    int b = batch[n];
    if (n == 0 || batch[n-1] != b) g_segs[b] = n;
    if (n == N-1 || batch[n+1] != b) g_sege[b] = n + 1;
}

// ---------------- message passing ----------------
// warp per edge; each lane loads one ea value, broadcast via shuffle
__global__ void edge_msg(const int* __restrict__ src, const int* __restrict__ dst,
                         const float* __restrict__ ea, int E) {
    int t = blockIdx.x * blockDim.x + threadIdx.x;
    int e = t >> 5, lane = t & 31;
    if (e >= E) return;
    int s = src[e], d = dst[e];
    const __half2* crow = (const __half2*)(g_ch + (size_t)s * CWC) + lane;
    float w = ea[(size_t)e * 16 + (lane & 15)];
    float2 acc = __half22float2(crow[16*32]);   // bias slot
#pragma unroll
    for (int k = 0; k < 16; k++) {
        float wk = __shfl_sync(0xffffffffu, w, k);
        float2 cc = __half22float2(crow[k*32]);
        acc.x += wk * cc.x;
        acc.y += wk * cc.y;
    }
    float* ap = g_aggr + (size_t)d*64 + lane*2;
    atomicAdd(ap, acc.x);
    atomicAdd(ap + 1, acc.y);
}

__global__ void gru_gate(const float* __restrict__ bih, const float* __restrict__ bhh, int N) {
    int t = blockIdx.x * blockDim.x + threadIdx.x;
    int n = t >> 6, o = t & 63;
    if (n >= N) return;
    const __half* gr = g_gh + (size_t)n * 256;
    float r = sigf(__half2float(gr[o]) + bih[o] + bhh[o]);
    float z = sigf(__half2float(gr[64 + o]) + bih[64 + o] + bhh[64 + o]);
    float ghn = __half2float(gr[192 + o]) + bhh[128 + o];
    float gin = __half2float(gr[128 + o]) - __half2float(gr[192 + o]) + bih[128 + o];
    float nn = tanhf(gin + r * ghn);
    float ho = g_h[(size_t)n*64 + o];
    g_h[(size_t)n*64 + o] = (1.f - z) * nn + z * ho;
}

// ---------------- node classifier ----------------
__global__ void p_kernel(const float* __restrict__ Wc, const float* __restrict__ bc,
                         float* __restrict__ out, int N) {
    int warp = (blockIdx.x * blockDim.x + threadIdx.x) >> 5;
    int lane = threadIdx.x & 31;
    if (warp >= N) return;
    const float* hr = g_h + (size_t)warp * 64;
    float s = hr[lane] * Wc[lane] + hr[32 + lane] * Wc[32 + lane];
#pragma unroll
    for (int o = 16; o; o >>= 1) s += __shfl_xor_sync(0xffffffffu, s, o);
    if (lane == 0) out[warp] = s + bc[0];
}

// ---------------- fused Set2Set step ----------------
// qh layout: [hs(128) | rvec(128)]
__global__ __launch_bounds__(128) void s2s_step(
    const float* __restrict__ bih, const float* __restrict__ bhh)
{
    int b = blockIdx.x;
    int t = threadIdx.x, wid = t >> 5, lane = t & 31;
    __shared__ float q[128];
    __shared__ float redm[4], redd[4];
    __shared__ float rvs[4][128];

    const float* g = g_gts + (size_t)b * 512;
    float ig = sigf(g[t]       + bih[t]       + bhh[t]);
    float fg = sigf(g[128 + t] + bih[128 + t] + bhh[128 + t]);
    float gg = tanhf(g[256 + t] + bih[256 + t] + bhh[256 + t]);
    float og = sigf(g[384 + t] + bih[384 + t] + bhh[384 + t]);
    float c = fg * g_cs[b*128 + t] + ig * gg;
    g_cs[b*128 + t] = c;
    float h = og * tanhf(c);
    q[t] = h;
    float* qh = g_qh + (size_t)b * 256;
    qh[t] = h;          // hs (== q)
    __syncthreads();

    int s0 = g_segs[b], s1 = g_sege[b];

    float mx = -INFINITY;
    for (int n = s0 + wid; n < s1; n += 4) {
        const float* h0r = g_h0 + (size_t)n * 64;
        const float* hr  = g_h  + (size_t)n * 64;
        float s = h0r[lane]*q[lane] + h0r[32+lane]*q[32+lane]
                + hr[lane]*q[64+lane] + hr[32+lane]*q[96+lane];
#pragma unroll
        for (int o = 16; o; o >>= 1) s += __shfl_xor_sync(0xffffffffu, s, o);
        mx = fmaxf(mx, s);
    }
    if (lane == 0) redm[wid] = mx;
    __syncthreads();
    mx = fmaxf(fmaxf(redm[0], redm[1]), fmaxf(redm[2], redm[3]));

    float den = 0.f, rv0 = 0.f, rv1 = 0.f, rv2 = 0.f, rv3 = 0.f;
    for (int n = s0 + wid; n < s1; n += 4) {
        const float* h0r = g_h0 + (size_t)n * 64;
        const float* hr  = g_h  + (size_t)n * 64;
        float x0 = h0r[lane], x1 = h0r[32+lane], x2 = hr[lane], x3 = hr[32+lane];
        float s = x0*q[lane] + x1*q[32+lane] + x2*q[64+lane] + x3*q[96+lane];
#pragma unroll
        for (int o = 16; o; o >>= 1) s += __shfl_xor_sync(0xffffffffu, s, o);
        float a = expf(s - mx);
        den += a;
        rv0 += a*x0; rv1 += a*x1; rv2 += a*x2; rv3 += a*x3;
    }
    rvs[wid][lane] = rv0; rvs[wid][32+lane] = rv1;
    rvs[wid][64+lane] = rv2; rvs[wid][96+lane] = rv3;
    if (lane == 0) redd[wid] = den;
    __syncthreads();
    float dtot = redd[0] + redd[1] + redd[2] + redd[3];
    float r = rvs[0][t] + rvs[1][t] + rvs[2][t] + rvs[3][t];
    qh[128 + t] = (s1 > s0) ? r / dtot : 0.f;
}

// ---------------- final regressor head ----------------
__global__ void head_kernel(const float* __restrict__ Wy1, const float* __restrict__ by1,
                            const float* __restrict__ Wy2, const float* __restrict__ by2,
                            float* __restrict__ out, int base, int B) {
    int b = blockIdx.x;
    int t = threadIdx.x;
    if (b >= B) return;
    __shared__ float sh_gf[1024];
    for (int i = t; i < 1024; i += 128) sh_gf[i] = g_gf[(size_t)b*1024 + i];
    __syncthreads();
    float s = by1[t];
    for (int r = 0; r < 1024; r++) s += sh_gf[r] * Wy1[r*128 + t];
    s = fmaxf(s, 0.f);
    float v = s * Wy2[t];
    __shared__ float red[128];
    red[t] = v;
    __syncthreads();
    for (int o = 64; o; o >>= 1) {
        if (t < o) red[t] += red[t + o];
        __syncthreads();
    }
    if (t == 0) out[base + b] = red[0] + by2[0];
}

// ---------------- host ----------------
extern "C" void kernel_launch(void* const* d_in, const int* in_sizes, int n_in,
                              void* d_out, int out_size) {
    const float* x         = (const float*)d_in[0];
    const int*   ei        = (const int*)  d_in[1];
    const float* edge_attr = (const float*)d_in[2];
    const int*   batch     = (const int*)  d_in[3];
    const float* W_proj    = (const float*)d_in[4];
    const float* b_proj    = (const float*)d_in[5];
    const float* W_edge    = (const float*)d_in[6];
    const float* b_edge    = (const float*)d_in[7];
    const float* root      = (const float*)d_in[8];
    const float* conv_bias = (const float*)d_in[9];
    const float* gru_W_ih  = (const float*)d_in[10];
    const float* gru_W_hh  = (const float*)d_in[11];
    const float* gru_b_ih  = (const float*)d_in[12];
    const float* gru_b_hh  = (const float*)d_in[13];
    const float* W_cls     = (const float*)d_in[14];
    const float* b_cls     = (const float*)d_in[15];
    const float* lstm_W_ih = (const float*)d_in[16];
    const float* lstm_W_hh = (const float*)d_in[17];
    const float* lstm_b_ih = (const float*)d_in[18];
    const float* lstm_b_hh = (const float*)d_in[19];
    const float* W_sp      = (const float*)d_in[20];
    const float* b_sp      = (const float*)d_in[21];
    const float* prelu_a   = (const float*)d_in[22];
    const float* W_y1      = (const float*)d_in[23];
    const float* b_y1      = (const float*)d_in[24];
    const float* W_y2      = (const float*)d_in[25];
    const float* b_y2      = (const float*)d_in[26];
    float* out = (float*)d_out;

    const int N = in_sizes[0] / 64;   // 30000
    const int E = in_sizes[2] / 16;   // 60000
    const int B = out_size - N;       // 500

    const int* src = ei;
    const int* dst = ei + E;

    float *p_h, *p_aggr, *p_B2L;
    float *p_qh, *p_cs, *p_gts, *p_gf;
    int *p_segs, *p_sege;
    __half *p_BtC, *p_Bt2_hi, *p_Bt2_lo, *p_BtP_hi, *p_BtP_lo;
    cudaGetSymbolAddress((void**)&p_h, g_h);
    cudaGetSymbolAddress((void**)&p_aggr, g_aggr);
    cudaGetSymbolAddress((void**)&p_B2L, g_B2L);
    cudaGetSymbolAddress((void**)&p_qh, g_qh);
    cudaGetSymbolAddress((void**)&p_cs, g_cs);
    cudaGetSymbolAddress((void**)&p_gts, g_gts);
    cudaGetSymbolAddress((void**)&p_gf, g_gf);
    cudaGetSymbolAddress((void**)&p_segs, g_segs);
    cudaGetSymbolAddress((void**)&p_sege, g_sege);
    cudaGetSymbolAddress((void**)&p_BtC, g_BtC);
    cudaGetSymbolAddress((void**)&p_Bt2_hi, g_Bt2_hi);
    cudaGetSymbolAddress((void**)&p_Bt2_lo, g_Bt2_lo);
    cudaGetSymbolAddress((void**)&p_BtP_hi, g_BtP_hi);
    cudaGetSymbolAddress((void**)&p_BtP_lo, g_BtP_lo);

    cudaFuncSetAttribute(cgemm_f16, cudaFuncAttributeMaxDynamicSharedMemorySize, 46080);
    cudaFuncSetAttribute(pgemm_f16, cudaFuncAttributeMaxDynamicSharedMemorySize, 36864);
    cudaFuncSetAttribute(ggemm_f16, cudaFuncAttributeMaxDynamicSharedMemorySize, 88064);

    // ---- prep + segment bounds ----
    prep_all<<<1200, 256>>>(W_edge, b_edge, root, gru_W_ih, gru_W_hh,
                            W_proj, lstm_W_ih, lstm_W_hh);
    cudaMemsetAsync(p_segs, 0, Bb*sizeof(int));
    cudaMemsetAsync(p_sege, 0, Bb*sizeof(int));
    seg_mark<<<(N + 255)/256, 256>>>(batch, N);

    const int gx = (N + 127) / 128;  // 235

    // ---- h0 = relu(x @ W_proj + b_proj) -> h0, h (fp16 2-pass) ----
    {
        dim3 grid(gx, 1);
        pgemm_f16<<<grid, 256, 36864>>>(x, p_BtP_hi, p_BtP_lo, N, b_proj);
    }

    // ---- message passing steps ----
    for (int step = 0; step < 3; step++) {
        {
            dim3 grid(gx, 6);
            cgemm_f16<<<grid, 256, 46080>>>(p_h, p_BtC, N, 3, conv_bias);
        }
        edge_msg<<<(E*32 + 255)/256, 256>>>(src, dst, edge_attr, E);
        {
            dim3 grid(gx, 2);
            ggemm_f16<<<grid, 256, 88064>>>(p_aggr, p_h, p_Bt2_hi, p_Bt2_lo, N, 2);
        }
        gru_gate<<<(N*64 + 255)/256, 256>>>(gru_b_ih, gru_b_hh, N);
    }

    // ---- node classifier ----
    p_kernel<<<(N*32 + 255)/256, 256>>>(W_cls, b_cls, out, N);

    // ---- Set2Set (fused, K=256 via hs-fold) ----
    cudaMemsetAsync(p_qh, 0, (size_t)B*256*sizeof(float));
    cudaMemsetAsync(p_cs, 0, (size_t)B*128*sizeof(float));

    const int gxb = (B + TBM - 1) / TBM;  // 4
    for (int step = 0; step < 3; step++) {
        {
            dim3 grid(gxb, 8);
            sgemm<<<grid, 256>>>(p_qh, 256, p_B2L, 512, p_gts, 512, B, 4, 0, nullptr, nullptr);
        }
        s2s_step<<<B, 128>>>(lstm_b_ih, lstm_b_hh);
    }

    // ---- final head ----
    {
        dim3 grid(gxb, 16);
        sgemm<<<grid, 256>>>(p_qh, 256, W_sp, 1024, p_gf, 1024, B, 4, 3, b_sp, prelu_a);
    }
    head_kernel<<<B, 128>>>(W_y1, b_y1, W_y2, b_y2, out, N, B);
}